// round 9
// baseline (speedup 1.0000x reference)
#include <cuda_runtime.h>
#include <math.h>
#include <stdint.h>

#define BB 32
#define FF 4096
#define HH 32
#define DD 128
#define LL 8192
#define NSPLIT 32
#define CH (LL/NSPLIT)          /* 256 */
#define WIN 64
#define LDW 72                  /* K window stride (floats) */
#define LDV 68                  /* V window stride (floats) */
#define LDP 68                  /* psh row stride (col 64 = corr) */
#define SCALE 0.08838834764831845f

/* ---------------- scratch ------------------------------------------------ */
__device__ float g_q[BB*HH*DD];
__device__ float g_k[BB*DD];
__device__ float g_v[BB*DD];
__device__ float g_attn[BB*HH*DD];
__device__ float g_pm[BB*NSPLIT*HH];
__device__ float g_psum[BB*NSPLIT*HH];
__device__ float g_po[BB*NSPLIT*HH*DD];
__device__ float g_freq[64];

/* ---------------- helpers ------------------------------------------------ */
__device__ __forceinline__ uint32_t s2u(const void* p) {
    return (uint32_t)__cvta_generic_to_shared(p);
}
__device__ __forceinline__ void cpa16(uint32_t s, const void* g) {
    asm volatile("cp.async.cg.shared.global [%0], [%1], 16;" :: "r"(s), "l"(g));
}
__device__ __forceinline__ void cpcommit() { asm volatile("cp.async.commit_group;"); }
__device__ __forceinline__ void cpwait0()  { asm volatile("cp.async.wait_group 0;"); }
__device__ __forceinline__ void cpwait1()  { asm volatile("cp.async.wait_group 1;"); }

__device__ __forceinline__ uint32_t f2tf(float x) {
    uint32_t r; asm("cvt.rna.tf32.f32 %0, %1;" : "=r"(r) : "f"(x)); return r;
}
__device__ __forceinline__ float tff(float x) { return __uint_as_float(f2tf(x)); }
__device__ __forceinline__ void mma8(float* d, const uint32_t* a, const uint32_t* b) {
    asm volatile("mma.sync.aligned.m16n8k8.row.col.f32.tf32.tf32.f32 "
        "{%0,%1,%2,%3},{%4,%5,%6,%7},{%8,%9},{%0,%1,%2,%3};"
        : "+f"(d[0]), "+f"(d[1]), "+f"(d[2]), "+f"(d[3])
        : "r"(a[0]), "r"(a[1]), "r"(a[2]), "r"(a[3]), "r"(b[0]), "r"(b[1]));
}

/* ---------------- zero + freq table -------------------------------------- */
__global__ void zero_kernel(float* __restrict__ out) {
    int i = blockIdx.x * 256 + threadIdx.x;
    g_q[i] = 0.f;
    out[i] = 0.f;
    if (i < BB*DD) { g_k[i] = 0.f; g_v[i] = 0.f; }
    if (i < 64) g_freq[i] = (float)exp(-(double)i * 0.14391156831212787);
}

/* ---------------- tensor GEMM v2 (3xTF32, 3-stage, 2 CTA/SM) --------------
 * C[32,N] += A[32,4096] * W[4096,N].  grid (N/128, 16), 256 thr = 8 warps.
 * N-tile 128 (warp covers 16 cols), split-K 16 (KSL=256, 8 kb-steps).
 * smem: As[256][33] | Ws 3 x [32][136]  = 86016 B -> 2 CTAs/SM.           */
#define SPLITK 16
#define KSL (FF/SPLITK)          /* 256 */
#define LDWS 136                 /* Ws row stride: 136%32==8 -> conflict-free */
#define WSTG 4352                /* floats per Ws stage (32*136) */
__global__ __launch_bounds__(256, 2) void tgemm32(
        const float* __restrict__ A, const float* __restrict__ W,
        float* __restrict__ C, int N) {
    extern __shared__ float sm[];
    float* As = sm;                  /* 8448 floats */
    float* Ws = sm + 8448;           /* 3 x 4352 floats */
    uint32_t ws_u = s2u(Ws);

    int n0 = blockIdx.x * 128;
    int k0 = blockIdx.y * KSL;
    int t = threadIdx.x, wp = t >> 5, lane = t & 31;
    int g = lane >> 2, c = lane & 3;

    /* A slice [32 x 256] -> As[k][m], one-time */
#pragma unroll
    for (int p = 0; p < 32; p++) {
        int i = t + p * 256;
        int m = i >> 8, k = i & 255;
        As[k * 33 + m] = A[m * FF + k0 + k];
    }
    auto loadW = [&](int kb, int buf) {
        const float* src = W + (size_t)(k0 + kb * 32) * N + n0;
#pragma unroll
        for (int p = 0; p < 4; p++) {
            int ci = t + p * 256;
            int kk = ci >> 5, u = ci & 31;
            cpa16(ws_u + (uint32_t)(buf * WSTG + kk * LDWS + 4 * u) * 4,
                  src + (size_t)kk * N + 4 * u);
        }
        cpcommit();
    };
    loadW(0, 0);
    loadW(1, 1);

    float acc[2][2][4];
#pragma unroll
    for (int mt = 0; mt < 2; mt++)
#pragma unroll
        for (int nt = 0; nt < 2; nt++)
#pragma unroll
            for (int r = 0; r < 4; r++) acc[mt][nt][r] = 0.f;

    for (int kb = 0; kb < 8; kb++) {
        if (kb == 7) cpwait0(); else cpwait1();
        __syncthreads();
        if (kb < 6) loadW(kb + 2, (kb + 2) % 3);
        const float* wsb = Ws + (kb % 3) * WSTG;

#pragma unroll
        for (int ks = 0; ks < 4; ks++) {
            int kg = kb * 32 + ks * 8;
            uint32_t ahi[2][4], alo[2][4];
#pragma unroll
            for (int mt = 0; mt < 2; mt++) {
                float a0 = As[(kg + c)     * 33 + mt * 16 + g];
                float a1 = As[(kg + c)     * 33 + mt * 16 + g + 8];
                float a2 = As[(kg + c + 4) * 33 + mt * 16 + g];
                float a3 = As[(kg + c + 4) * 33 + mt * 16 + g + 8];
                ahi[mt][0] = f2tf(a0); alo[mt][0] = f2tf(a0 - __uint_as_float(ahi[mt][0]));
                ahi[mt][1] = f2tf(a1); alo[mt][1] = f2tf(a1 - __uint_as_float(ahi[mt][1]));
                ahi[mt][2] = f2tf(a2); alo[mt][2] = f2tf(a2 - __uint_as_float(ahi[mt][2]));
                ahi[mt][3] = f2tf(a3); alo[mt][3] = f2tf(a3 - __uint_as_float(ahi[mt][3]));
            }
#pragma unroll
            for (int nt = 0; nt < 2; nt++) {
                float b0 = wsb[(ks * 8 + c)     * LDWS + wp * 16 + nt * 8 + g];
                float b1 = wsb[(ks * 8 + c + 4) * LDWS + wp * 16 + nt * 8 + g];
                uint32_t bhi[2], blo[2];
                bhi[0] = f2tf(b0); blo[0] = f2tf(b0 - __uint_as_float(bhi[0]));
                bhi[1] = f2tf(b1); blo[1] = f2tf(b1 - __uint_as_float(bhi[1]));
#pragma unroll
                for (int mt = 0; mt < 2; mt++) {
                    mma8(acc[mt][nt], ahi[mt], bhi);
                    mma8(acc[mt][nt], ahi[mt], blo);
                    mma8(acc[mt][nt], alo[mt], bhi);
                }
            }
        }
    }
#pragma unroll
    for (int mt = 0; mt < 2; mt++)
#pragma unroll
        for (int nt = 0; nt < 2; nt++) {
            int row = mt * 16 + g;
            int col = n0 + wp * 16 + nt * 8 + 2 * c;
            atomicAdd(&C[(row)     * N + col],     acc[mt][nt][0]);
            atomicAdd(&C[(row)     * N + col + 1], acc[mt][nt][1]);
            atomicAdd(&C[(row + 8) * N + col],     acc[mt][nt][2]);
            atomicAdd(&C[(row + 8) * N + col + 1], acc[mt][nt][3]);
        }
}

/* ---------------- k/v projection ----------------------------------------- */
__global__ __launch_bounds__(256) void kvproj(
        const float* __restrict__ A, const float* __restrict__ Wk,
        const float* __restrict__ Wv) {
    __shared__ float As[32][36];
    __shared__ float Ws[32][132];
    const float* W = blockIdx.x ? Wv : Wk;
    float* C = blockIdx.x ? g_v : g_k;
    int k0 = blockIdx.y * 128;
    int t = threadIdx.x;
    int mi = t >> 5, ni = t & 31;
    float acc[4][4];
#pragma unroll
    for (int i = 0; i < 4; i++)
#pragma unroll
        for (int j = 0; j < 4; j++) acc[i][j] = 0.f;

    for (int kb = 0; kb < 128; kb += 32) {
        int kg = k0 + kb;
#pragma unroll
        for (int p = 0; p < 4; p++) {
            int i = t + p * 256;
            As[i & 31][i >> 5] = A[(i >> 5) * FF + kg + (i & 31)];
        }
#pragma unroll
        for (int p = 0; p < 4; p++) {
            int i = t + p * 256;
            int kk = i >> 5, nq = i & 31;
            *(float4*)&Ws[kk][nq * 4] = *(const float4*)&W[(kg + kk) * DD + nq * 4];
        }
        __syncthreads();
#pragma unroll
        for (int kk = 0; kk < 32; kk++) {
            float4 a = *(float4*)&As[kk][mi * 4];
            float4 w = *(float4*)&Ws[kk][ni * 4];
            acc[0][0] += a.x*w.x; acc[0][1] += a.x*w.y; acc[0][2] += a.x*w.z; acc[0][3] += a.x*w.w;
            acc[1][0] += a.y*w.x; acc[1][1] += a.y*w.y; acc[1][2] += a.y*w.z; acc[1][3] += a.y*w.w;
            acc[2][0] += a.z*w.x; acc[2][1] += a.z*w.y; acc[2][2] += a.z*w.z; acc[2][3] += a.z*w.w;
            acc[3][0] += a.w*w.x; acc[3][1] += a.w*w.y; acc[3][2] += a.w*w.z; acc[3][3] += a.w*w.w;
        }
        __syncthreads();
    }
#pragma unroll
    for (int i = 0; i < 4; i++)
#pragma unroll
        for (int j = 0; j < 4; j++)
            atomicAdd(&C[(mi * 4 + i) * DD + ni * 4 + j], acc[i][j]);
}

/* ---------------- flash-decode attention v4 (unchanged from R8) ----------- */
__global__ __launch_bounds__(256, 2) void attn_kernel(
        const float* __restrict__ Kc, const float* __restrict__ Vc,
        const int* __restrict__ ci) {
    extern __shared__ float sm[];
    float4* qfh4 = (float4*)sm;
    float4* qfl4 = qfh4 + 1024;
    float*  psh  = sm + 8192;
    float*  kbuf = sm + 10368;
    float*  vbuf = sm + 19584;

    int b = blockIdx.x, sp = blockIdx.y;
    int idx = ci[b];
    int c0  = sp * CH;
    if (c0 > idx) return;

    int t = threadIdx.x, w = t >> 5, lane = t & 31;
    int g = lane >> 2, c = lane & 3;
    float pos = (float)idx;

    const float* Kb = Kc + (size_t)b * DD * LL;
    const float* Vb = Vc + (size_t)b * DD * LL;

    auto fillK = [&](int wi) {
        uint32_t dst = s2u(kbuf);
        const float* src = Kb + c0 + wi * WIN;
#pragma unroll
        for (int p = 0; p < 8; p++) {
            int i = t + p * 256; int d = i >> 4, u = i & 15;
            cpa16(dst + (uint32_t)(d * LDW + 4 * u) * 4, src + (size_t)d * LL + 4 * u);
        }
        cpcommit();
    };
    auto fillV = [&](int wi) {
        uint32_t dst = s2u(vbuf);
        const float* src = Vb + c0 + wi * WIN;
#pragma unroll
        for (int p = 0; p < 8; p++) {
            int i = t + p * 256; int d = i >> 4, u = i & 15;
            cpa16(dst + (uint32_t)(d * LDV + 4 * u) * 4, src + (size_t)d * LL + 4 * u);
        }
        cpcommit();
    };

    fillK(0);
    fillV(0);

    /* q -> rope -> scale -> 2-term tf32, swizzled fragment layout */
#pragma unroll
    for (int p = 0; p < 4; p++) {
        int fid = p * 256 + t;
        int kd = fid >> 6, mt = (fid >> 5) & 1, cc = (fid >> 3) & 3, gg = fid & 7;
        int r0 = mt * 16 + gg, r1 = r0 + 8;
        const float* qb = g_q + b * HH * DD;
        float4 hi, lo;
        float e[4];
#pragma unroll
        for (int dj = 0; dj < 2; dj++) {
            int dcol = 8 * kd + cc + 4 * dj;
            float si, co;
            sincosf(pos * g_freq[dcol & 63], &si, &co);
#pragma unroll
            for (int rj = 0; rj < 2; rj++) {
                int r = rj ? r1 : r0;
                float a = qb[r * DD + dcol];
                float o = qb[r * DD + (dcol ^ 64)];
                float v = (dcol < 64) ? (a * co - o * si) : (a * co + o * si);
                e[dj * 2 + rj] = v * SCALE;
            }
        }
        hi.x = tff(e[0]); lo.x = tff(e[0] - hi.x);
        hi.y = tff(e[1]); lo.y = tff(e[1] - hi.y);
        hi.z = tff(e[2]); lo.z = tff(e[2] - hi.z);
        hi.w = tff(e[3]); lo.w = tff(e[3] - hi.w);
        int sfid = kd * 64 + mt * 32 + cc * 8 + ((gg + 2 * cc) & 7);
        qfh4[sfid] = hi;
        qfl4[sfid] = lo;
    }
    __syncthreads();

    int swz = c * 8 + ((g + 2 * c) & 7);

    float m_r[4] = {-1e30f, -1e30f, -1e30f, -1e30f};
    float s_r[4] = {0.f, 0.f, 0.f, 0.f};
    float acco[2][2][4];
#pragma unroll
    for (int mt = 0; mt < 2; mt++)
#pragma unroll
        for (int nt = 0; nt < 2; nt++)
#pragma unroll
            for (int r = 0; r < 4; r++) acco[mt][nt][r] = 0.f;

    for (int wi = 0; wi < 4; wi++) {
        int l0w = c0 + wi * WIN;
        int hot = (idx >= l0w) && (idx < l0w + WIN);
        int li = idx - l0w;

        cpwait1();
        __syncthreads();
        if (hot) {
            if (t < 128) {
                float si, co;
                sincosf(pos * g_freq[t & 63], &si, &co);
                float a = g_k[b * DD + t];
                float o = g_k[b * DD + (t ^ 64)];
                float kr = (t < 64) ? (a * co - o * si) : (a * co + o * si);
                kbuf[t * LDW + li] += kr;
            }
            __syncthreads();
        }

        /* ---- QK: warp w -> window l-cols [8w, 8w+8) ---- */
        float accq[2][4];
#pragma unroll
        for (int mt = 0; mt < 2; mt++)
#pragma unroll
            for (int r = 0; r < 4; r++) accq[mt][r] = 0.f;

#pragma unroll
        for (int kd = 0; kd < 16; kd++) {
            float4 ah0 = qfh4[kd * 64 +      swz];
            float4 ah1 = qfh4[kd * 64 + 32 + swz];
            float4 al0 = qfl4[kd * 64 +      swz];
            float4 al1 = qfl4[kd * 64 + 32 + swz];
            float b0 = kbuf[(kd * 8 + c)     * LDW + w * 8 + g];
            float b1 = kbuf[(kd * 8 + c + 4) * LDW + w * 8 + g];
            uint32_t bb[2] = {f2tf(b0), f2tf(b1)};
            mma8(accq[0], (const uint32_t*)&ah0, bb);
            mma8(accq[0], (const uint32_t*)&al0, bb);
            mma8(accq[1], (const uint32_t*)&ah1, bb);
            mma8(accq[1], (const uint32_t*)&al1, bb);
        }
#pragma unroll
        for (int mt = 0; mt < 2; mt++) {
            int r0 = mt * 16 + g, cb = w * 8 + 2 * c;
            psh[r0 * LDP + cb]           = accq[mt][0];
            psh[r0 * LDP + cb + 1]       = accq[mt][1];
            psh[(r0 + 8) * LDP + cb]     = accq[mt][2];
            psh[(r0 + 8) * LDP + cb + 1] = accq[mt][3];
        }
        __syncthreads();
        if (wi < 3) fillK(wi + 1);

        /* ---- online softmax ---- */
#pragma unroll
        for (int hj = 0; hj < 4; hj++) {
            int h = 4 * w + hj;
            float2 f = *(float2*)&psh[h * LDP + 2 * lane];
            if (l0w + WIN - 1 > idx) {
                int lb = l0w + 2 * lane;
                if (lb     > idx) f.x = -1e30f;
                if (lb + 1 > idx) f.y = -1e30f;
            }
            float tm = fmaxf(f.x, f.y);
            tm = fmaxf(tm, __shfl_xor_sync(0xffffffffu, tm, 16));
            tm = fmaxf(tm, __shfl_xor_sync(0xffffffffu, tm, 8));
            tm = fmaxf(tm, __shfl_xor_sync(0xffffffffu, tm, 4));
            tm = fmaxf(tm, __shfl_xor_sync(0xffffffffu, tm, 2));
            tm = fmaxf(tm, __shfl_xor_sync(0xffffffffu, tm, 1));
            float mn = fmaxf(m_r[hj], tm);
            float co = __expf(m_r[hj] - mn);
            float p0 = __expf(f.x - mn), p1 = __expf(f.y - mn);
            float ls = p0 + p1;
            ls += __shfl_xor_sync(0xffffffffu, ls, 16);
            ls += __shfl_xor_sync(0xffffffffu, ls, 8);
            ls += __shfl_xor_sync(0xffffffffu, ls, 4);
            ls += __shfl_xor_sync(0xffffffffu, ls, 2);
            ls += __shfl_xor_sync(0xffffffffu, ls, 1);
            s_r[hj] = s_r[hj] * co + ls;
            m_r[hj] = mn;
            *(float2*)&psh[h * LDP + 2 * lane] = make_float2(tff(p0), tff(p1));
            if (lane == 0) psh[h * LDP + 64] = co;
        }

        if (wi == 3) cpwait0(); else cpwait1();
        __syncthreads();
        if (hot) {
            if (t < 128) vbuf[t * LDV + li] += g_v[b * DD + t];
            __syncthreads();
        }

        /* rescale PV accumulators */
        {
            float s0 = psh[(g)      * LDP + 64];
            float s1 = psh[(g + 8)  * LDP + 64];
            float s2 = psh[(g + 16) * LDP + 64];
            float s3 = psh[(g + 24) * LDP + 64];
#pragma unroll
            for (int nt = 0; nt < 2; nt++) {
                acco[0][nt][0] *= s0; acco[0][nt][1] *= s0;
                acco[0][nt][2] *= s1; acco[0][nt][3] *= s1;
                acco[1][nt][0] *= s2; acco[1][nt][1] *= s2;
                acco[1][nt][2] *= s3; acco[1][nt][3] *= s3;
            }
        }

        /* ---- PV: warp w -> d [16w, 16w+16) ---- */
#pragma unroll
        for (int kl = 0; kl < 8; kl++) {
            int lb0 = kl * 8 + c;
            uint32_t ap0[4], ap1[4];
            ap0[0] = __float_as_uint(psh[(g)      * LDP + lb0]);
            ap0[1] = __float_as_uint(psh[(g + 8)  * LDP + lb0]);
            ap0[2] = __float_as_uint(psh[(g)      * LDP + lb0 + 4]);
            ap0[3] = __float_as_uint(psh[(g + 8)  * LDP + lb0 + 4]);
            ap1[0] = __float_as_uint(psh[(g + 16) * LDP + lb0]);
            ap1[1] = __float_as_uint(psh[(g + 24) * LDP + lb0]);
            ap1[2] = __float_as_uint(psh[(g + 16) * LDP + lb0 + 4]);
            ap1[3] = __float_as_uint(psh[(g + 24) * LDP + lb0 + 4]);
#pragma unroll
            for (int nt = 0; nt < 2; nt++) {
                int d = w * 16 + nt * 8 + g;
                float v0 = vbuf[d * LDV + kl * 8 + c];
                float v1 = vbuf[d * LDV + kl * 8 + c + 4];
                uint32_t bh[2], bl[2];
                bh[0] = f2tf(v0); bl[0] = f2tf(v0 - __uint_as_float(bh[0]));
                bh[1] = f2tf(v1); bl[1] = f2tf(v1 - __uint_as_float(bh[1]));
                mma8(acco[0][nt], ap0, bh);
                mma8(acco[0][nt], ap0, bl);
                mma8(acco[1][nt], ap1, bh);
                mma8(acco[1][nt], ap1, bl);
            }
        }
        __syncthreads();
        if (wi < 3) fillV(wi + 1);
    }

    /* write partials */
    int pb = (b * NSPLIT + sp) * HH;
    if (lane == 0) {
#pragma unroll
        for (int hj = 0; hj < 4; hj++) {
            g_pm[pb + 4 * w + hj]   = m_r[hj];
            g_psum[pb + 4 * w + hj] = s_r[hj];
        }
    }
#pragma unroll
    for (int mt = 0; mt < 2; mt++)
#pragma unroll
        for (int nt = 0; nt < 2; nt++) {
            int h0 = mt * 16 + g;
            int dd = w * 16 + nt * 8 + 2 * c;
            g_po[(size_t)(pb + h0) * DD + dd]         = acco[mt][nt][0];
            g_po[(size_t)(pb + h0) * DD + dd + 1]     = acco[mt][nt][1];
            g_po[(size_t)(pb + h0 + 8) * DD + dd]     = acco[mt][nt][2];
            g_po[(size_t)(pb + h0 + 8) * DD + dd + 1] = acco[mt][nt][3];
        }
}

/* ---------------- combine (validity-aware) ------------------------------- */
__global__ void combine_kernel(const int* __restrict__ ci) {
    int bh = blockIdx.x;
    int b = bh >> 5, h = bh & 31;
    int d = threadIdx.x;
    int nv = (ci[b] >> 8) + 1;
    float m = -1e30f;
    for (int s = 0; s < nv; s++)
        m = fmaxf(m, g_pm[(b * NSPLIT + s) * HH + h]);
    float S = 0.f, acc = 0.f;
    for (int s = 0; s < nv; s++) {
        int ib = (b * NSPLIT + s) * HH + h;
        float w = __expf(g_pm[ib] - m);
        S   += w * g_psum[ib];
        acc += w * g_po[(size_t)ib * DD + d];
    }
    g_attn[(b * HH + h) * DD + d] = acc / S;
}

/* ---------------- launch ------------------------------------------------- */
extern "C" void kernel_launch(void* const* d_in, const int* in_sizes, int n_in,
                              void* d_out, int out_size) {
    const float* x  = (const float*)d_in[0];
    const float* Kc = (const float*)d_in[1];
    const float* Vc = (const float*)d_in[2];
    const float* Wq = (const float*)d_in[3];
    const float* Wk = (const float*)d_in[4];
    const float* Wv = (const float*)d_in[5];
    const float* Wo = (const float*)d_in[6];
    const int*   ci = (const int*)d_in[7];
    float* out = (float*)d_out;

    float *qp, *ap;
    cudaGetSymbolAddress((void**)&qp, g_q);
    cudaGetSymbolAddress((void**)&ap, g_attn);

    cudaFuncSetAttribute(tgemm32,
                         cudaFuncAttributeMaxDynamicSharedMemorySize, 86016);
    cudaFuncSetAttribute(attn_kernel,
                         cudaFuncAttributeMaxDynamicSharedMemorySize, 113152);

    zero_kernel<<<512, 256>>>(out);
    tgemm32<<<dim3(32, SPLITK), 256, 86016>>>(x, Wq, qp, 4096);
    kvproj<<<dim3(2, 32), 256>>>(x, Wk, Wv);
    attn_kernel<<<dim3(32, NSPLIT), 256, 113152>>>(Kc, Vc, ci);
    combine_kernel<<<1024, 128>>>(ci);
    tgemm32<<<dim3(32, SPLITK), 256, 86016>>>(ap, Wo, out, 4096);
}

// round 10
// speedup vs baseline: 1.0791x; 1.0791x over previous
#include <cuda_runtime.h>
#include <math.h>
#include <stdint.h>

#define BB 32
#define FF 4096
#define HH 32
#define DD 128
#define LL 8192
#define NSPLIT 32
#define CH (LL/NSPLIT)          /* 256 */
#define WIN 64
#define LDW 72                  /* K window stride (floats) */
#define LDV 68                  /* V window stride (floats) */
#define LDP 68                  /* psh row stride (col 64 = corr) */
#define SCALE 0.08838834764831845f

/* ---------------- scratch ------------------------------------------------ */
__device__ float g_q[BB*HH*DD];
__device__ float g_k[BB*DD];
__device__ float g_v[BB*DD];
__device__ float g_attn[BB*HH*DD];
__device__ float g_pm[BB*NSPLIT*HH];
__device__ float g_psum[BB*NSPLIT*HH];
__device__ float g_po[BB*NSPLIT*HH*DD];
__device__ float g_freq[64];

/* ---------------- helpers ------------------------------------------------ */
__device__ __forceinline__ uint32_t s2u(const void* p) {
    return (uint32_t)__cvta_generic_to_shared(p);
}
__device__ __forceinline__ void cpa16(uint32_t s, const void* g) {
    asm volatile("cp.async.cg.shared.global [%0], [%1], 16;" :: "r"(s), "l"(g));
}
__device__ __forceinline__ void cpcommit() { asm volatile("cp.async.commit_group;"); }
__device__ __forceinline__ void cpwait0()  { asm volatile("cp.async.wait_group 0;"); }
__device__ __forceinline__ void cpwait1()  { asm volatile("cp.async.wait_group 1;"); }

__device__ __forceinline__ uint32_t f2tf(float x) {
    uint32_t r; asm("cvt.rna.tf32.f32 %0, %1;" : "=r"(r) : "f"(x)); return r;
}
__device__ __forceinline__ float tff(float x) { return __uint_as_float(f2tf(x)); }
__device__ __forceinline__ void mma8(float* d, const uint32_t* a, const uint32_t* b) {
    asm volatile("mma.sync.aligned.m16n8k8.row.col.f32.tf32.tf32.f32 "
        "{%0,%1,%2,%3},{%4,%5,%6,%7},{%8,%9},{%0,%1,%2,%3};"
        : "+f"(d[0]), "+f"(d[1]), "+f"(d[2]), "+f"(d[3])
        : "r"(a[0]), "r"(a[1]), "r"(a[2]), "r"(a[3]), "r"(b[0]), "r"(b[1]));
}

/* ---------------- zero + freq table -------------------------------------- */
__global__ void zero_kernel(float* __restrict__ out) {
    int i = blockIdx.x * 256 + threadIdx.x;
    g_q[i] = 0.f;
    out[i] = 0.f;
    if (i < BB*DD) { g_k[i] = 0.f; g_v[i] = 0.f; }
    if (i < 64) g_freq[i] = (float)exp(-(double)i * 0.14391156831212787);
}

/* ---------------- tensor GEMM (3xTF32, 3-stage, R8 config) ---------------- */
#define SPLITK 8
#define KSL (FF/SPLITK)          /* 512 */
__global__ __launch_bounds__(256) void tgemm32(
        const float* __restrict__ A, const float* __restrict__ W,
        float* __restrict__ C, int N) {
    extern __shared__ float sm[];
    float* As = sm;                  /* 16896 floats */
    float* Ws = sm + 16896;          /* 3 x 8448 floats */
    uint32_t ws_u = s2u(Ws);

    int n0 = blockIdx.x * 256;
    int k0 = blockIdx.y * KSL;
    int t = threadIdx.x, wp = t >> 5, lane = t & 31;
    int g = lane >> 2, c = lane & 3;

#pragma unroll
    for (int p = 0; p < 64; p++) {
        int i = t + p * 256;
        int m = i >> 9, k = i & 511;
        As[k * 33 + m] = A[m * FF + k0 + k];
    }
    auto loadW = [&](int kb, int buf) {
        const float* src = W + (size_t)(k0 + kb * 32) * N + n0;
#pragma unroll
        for (int p = 0; p < 8; p++) {
            int ci = t + p * 256;
            int kk = ci >> 6, u = ci & 63;
            cpa16(ws_u + (uint32_t)(buf * 8448 + kk * 264 + 4 * u) * 4,
                  src + (size_t)kk * N + 4 * u);
        }
        cpcommit();
    };
    loadW(0, 0);
    loadW(1, 1);

    float acc[2][4][4];
#pragma unroll
    for (int mt = 0; mt < 2; mt++)
#pragma unroll
        for (int nt = 0; nt < 4; nt++)
#pragma unroll
            for (int r = 0; r < 4; r++) acc[mt][nt][r] = 0.f;

    for (int kb = 0; kb < 16; kb++) {
        if (kb == 15) cpwait0(); else cpwait1();
        __syncthreads();
        if (kb < 14) loadW(kb + 2, (kb + 2) % 3);
        const float* wsb = Ws + (kb % 3) * 8448;

#pragma unroll
        for (int ks = 0; ks < 4; ks++) {
            int kg = kb * 32 + ks * 8;
            uint32_t ahi[2][4], alo[2][4];
#pragma unroll
            for (int mt = 0; mt < 2; mt++) {
                float a0 = As[(kg + c)     * 33 + mt * 16 + g];
                float a1 = As[(kg + c)     * 33 + mt * 16 + g + 8];
                float a2 = As[(kg + c + 4) * 33 + mt * 16 + g];
                float a3 = As[(kg + c + 4) * 33 + mt * 16 + g + 8];
                ahi[mt][0] = f2tf(a0); alo[mt][0] = f2tf(a0 - __uint_as_float(ahi[mt][0]));
                ahi[mt][1] = f2tf(a1); alo[mt][1] = f2tf(a1 - __uint_as_float(ahi[mt][1]));
                ahi[mt][2] = f2tf(a2); alo[mt][2] = f2tf(a2 - __uint_as_float(ahi[mt][2]));
                ahi[mt][3] = f2tf(a3); alo[mt][3] = f2tf(a3 - __uint_as_float(ahi[mt][3]));
            }
#pragma unroll
            for (int nt = 0; nt < 4; nt++) {
                float b0 = wsb[(ks * 8 + c)     * 264 + wp * 32 + nt * 8 + g];
                float b1 = wsb[(ks * 8 + c + 4) * 264 + wp * 32 + nt * 8 + g];
                uint32_t bhi[2], blo[2];
                bhi[0] = f2tf(b0); blo[0] = f2tf(b0 - __uint_as_float(bhi[0]));
                bhi[1] = f2tf(b1); blo[1] = f2tf(b1 - __uint_as_float(bhi[1]));
#pragma unroll
                for (int mt = 0; mt < 2; mt++) {
                    mma8(acc[mt][nt], ahi[mt], bhi);
                    mma8(acc[mt][nt], ahi[mt], blo);
                    mma8(acc[mt][nt], alo[mt], bhi);
                }
            }
        }
    }
#pragma unroll
    for (int mt = 0; mt < 2; mt++)
#pragma unroll
        for (int nt = 0; nt < 4; nt++) {
            int row = mt * 16 + g;
            int col = n0 + wp * 32 + nt * 8 + 2 * c;
            atomicAdd(&C[(row)     * N + col],     acc[mt][nt][0]);
            atomicAdd(&C[(row)     * N + col + 1], acc[mt][nt][1]);
            atomicAdd(&C[(row + 8) * N + col],     acc[mt][nt][2]);
            atomicAdd(&C[(row + 8) * N + col + 1], acc[mt][nt][3]);
        }
}

/* ---------------- k/v projection ----------------------------------------- */
__global__ __launch_bounds__(256) void kvproj(
        const float* __restrict__ A, const float* __restrict__ Wk,
        const float* __restrict__ Wv) {
    __shared__ float As[32][36];
    __shared__ float Ws[32][132];
    const float* W = blockIdx.x ? Wv : Wk;
    float* C = blockIdx.x ? g_v : g_k;
    int k0 = blockIdx.y * 128;
    int t = threadIdx.x;
    int mi = t >> 5, ni = t & 31;
    float acc[4][4];
#pragma unroll
    for (int i = 0; i < 4; i++)
#pragma unroll
        for (int j = 0; j < 4; j++) acc[i][j] = 0.f;

    for (int kb = 0; kb < 128; kb += 32) {
        int kg = k0 + kb;
#pragma unroll
        for (int p = 0; p < 4; p++) {
            int i = t + p * 256;
            As[i & 31][i >> 5] = A[(i >> 5) * FF + kg + (i & 31)];
        }
#pragma unroll
        for (int p = 0; p < 4; p++) {
            int i = t + p * 256;
            int kk = i >> 5, nq = i & 31;
            *(float4*)&Ws[kk][nq * 4] = *(const float4*)&W[(kg + kk) * DD + nq * 4];
        }
        __syncthreads();
#pragma unroll
        for (int kk = 0; kk < 32; kk++) {
            float4 a = *(float4*)&As[kk][mi * 4];
            float4 w = *(float4*)&Ws[kk][ni * 4];
            acc[0][0] += a.x*w.x; acc[0][1] += a.x*w.y; acc[0][2] += a.x*w.z; acc[0][3] += a.x*w.w;
            acc[1][0] += a.y*w.x; acc[1][1] += a.y*w.y; acc[1][2] += a.y*w.z; acc[1][3] += a.y*w.w;
            acc[2][0] += a.z*w.x; acc[2][1] += a.z*w.y; acc[2][2] += a.z*w.z; acc[2][3] += a.z*w.w;
            acc[3][0] += a.w*w.x; acc[3][1] += a.w*w.y; acc[3][2] += a.w*w.z; acc[3][3] += a.w*w.w;
        }
        __syncthreads();
    }
#pragma unroll
    for (int i = 0; i < 4; i++)
#pragma unroll
        for (int j = 0; j < 4; j++)
            atomicAdd(&C[(mi * 4 + i) * DD + ni * 4 + j], acc[i][j]);
}

/* ---------------- flash-decode attention v5 --------------------------------
 * v4 + (a) single-term tf32 q, (b) fragment-packed probabilities so PV
 * A-loads are 2 x LDS.128 per k-step.
 * smem floats: qfh 4096 | psh 32x68 | ppack 2048 | kbuf 9216 | vbuf 8704
 *            = 26240 floats = 104,960 B -> 2 CTAs/SM.                     */
__global__ __launch_bounds__(256, 2) void attn_kernel(
        const float* __restrict__ Kc, const float* __restrict__ Vc,
        const int* __restrict__ ci) {
    extern __shared__ float sm[];
    float4* qfh4 = (float4*)sm;                 /* 1024 float4 */
    float*  psh  = sm + 4096;                   /* 2176 */
    float*  ppkf = sm + 6272;                   /* 2048 (scalar view) */
    float4* ppk4 = (float4*)ppkf;               /* 512 float4 */
    float*  kbuf = sm + 8320;                   /* 9216 */
    float*  vbuf = sm + 17536;                  /* 8704 */

    int b = blockIdx.x, sp = blockIdx.y;
    int idx = ci[b];
    int c0  = sp * CH;
    if (c0 > idx) return;

    int t = threadIdx.x, w = t >> 5, lane = t & 31;
    int g = lane >> 2, c = lane & 3;
    float pos = (float)idx;

    const float* Kb = Kc + (size_t)b * DD * LL;
    const float* Vb = Vc + (size_t)b * DD * LL;

    auto fillK = [&](int wi) {
        uint32_t dst = s2u(kbuf);
        const float* src = Kb + c0 + wi * WIN;
#pragma unroll
        for (int p = 0; p < 8; p++) {
            int i = t + p * 256; int d = i >> 4, u = i & 15;
            cpa16(dst + (uint32_t)(d * LDW + 4 * u) * 4, src + (size_t)d * LL + 4 * u);
        }
        cpcommit();
    };
    auto fillV = [&](int wi) {
        uint32_t dst = s2u(vbuf);
        const float* src = Vb + c0 + wi * WIN;
#pragma unroll
        for (int p = 0; p < 8; p++) {
            int i = t + p * 256; int d = i >> 4, u = i & 15;
            cpa16(dst + (uint32_t)(d * LDV + 4 * u) * 4, src + (size_t)d * LL + 4 * u);
        }
        cpcommit();
    };

    fillK(0);
    fillV(0);

    /* q -> rope -> scale -> single tf32, swizzled fragment layout */
#pragma unroll
    for (int p = 0; p < 4; p++) {
        int fid = p * 256 + t;
        int kd = fid >> 6, mt = (fid >> 5) & 1, cc = (fid >> 3) & 3, gg = fid & 7;
        int r0 = mt * 16 + gg, r1 = r0 + 8;
        const float* qb = g_q + b * HH * DD;
        float4 hi;
        float e[4];
#pragma unroll
        for (int dj = 0; dj < 2; dj++) {
            int dcol = 8 * kd + cc + 4 * dj;
            float si, co;
            sincosf(pos * g_freq[dcol & 63], &si, &co);
#pragma unroll
            for (int rj = 0; rj < 2; rj++) {
                int r = rj ? r1 : r0;
                float a = qb[r * DD + dcol];
                float o = qb[r * DD + (dcol ^ 64)];
                float v = (dcol < 64) ? (a * co - o * si) : (a * co + o * si);
                e[dj * 2 + rj] = v * SCALE;
            }
        }
        hi.x = tff(e[0]); hi.y = tff(e[1]); hi.z = tff(e[2]); hi.w = tff(e[3]);
        int sfid = kd * 64 + mt * 32 + cc * 8 + ((gg + 2 * cc) & 7);
        qfh4[sfid] = hi;
    }
    __syncthreads();

    int swz = c * 8 + ((g + 2 * c) & 7);

    float m_r[4] = {-1e30f, -1e30f, -1e30f, -1e30f};
    float s_r[4] = {0.f, 0.f, 0.f, 0.f};
    float acco[2][2][4];
#pragma unroll
    for (int mt = 0; mt < 2; mt++)
#pragma unroll
        for (int nt = 0; nt < 2; nt++)
#pragma unroll
            for (int r = 0; r < 4; r++) acco[mt][nt][r] = 0.f;

    for (int wi = 0; wi < 4; wi++) {
        int l0w = c0 + wi * WIN;
        int hot = (idx >= l0w) && (idx < l0w + WIN);
        int li = idx - l0w;

        cpwait1();                  /* K_wi ready (V_wi pending) */
        __syncthreads();
        if (hot) {
            if (t < 128) {
                float si, co;
                sincosf(pos * g_freq[t & 63], &si, &co);
                float a = g_k[b * DD + t];
                float o = g_k[b * DD + (t ^ 64)];
                float kr = (t < 64) ? (a * co - o * si) : (a * co + o * si);
                kbuf[t * LDW + li] += kr;
            }
            __syncthreads();
        }

        /* ---- QK: warp w -> window l-cols [8w, 8w+8) ---- */
        float accq[2][4];
#pragma unroll
        for (int mt = 0; mt < 2; mt++)
#pragma unroll
            for (int r = 0; r < 4; r++) accq[mt][r] = 0.f;

#pragma unroll
        for (int kd = 0; kd < 16; kd++) {
            float4 ah0 = qfh4[kd * 64 +      swz];
            float4 ah1 = qfh4[kd * 64 + 32 + swz];
            float b0 = kbuf[(kd * 8 + c)     * LDW + w * 8 + g];
            float b1 = kbuf[(kd * 8 + c + 4) * LDW + w * 8 + g];
            uint32_t bb[2] = {f2tf(b0), f2tf(b1)};
            mma8(accq[0], (const uint32_t*)&ah0, bb);
            mma8(accq[1], (const uint32_t*)&ah1, bb);
        }
#pragma unroll
        for (int mt = 0; mt < 2; mt++) {
            int r0 = mt * 16 + g, cb = w * 8 + 2 * c;
            psh[r0 * LDP + cb]           = accq[mt][0];
            psh[r0 * LDP + cb + 1]       = accq[mt][1];
            psh[(r0 + 8) * LDP + cb]     = accq[mt][2];
            psh[(r0 + 8) * LDP + cb + 1] = accq[mt][3];
        }
        __syncthreads();            /* logits visible; kbuf free */
        if (wi < 3) fillK(wi + 1);

        /* ---- online softmax; probs stored fragment-packed into ppack ----
         * ppack float4 index: kl*64 + half*32 + ((g+kl)&7)*4 + ((c+(kl>>1))&3)
         * components: x=(mt0,k lo), y=(mt1,k lo), z=(mt0,k hi), w=(mt1,k hi) */
#pragma unroll
        for (int hj = 0; hj < 4; hj++) {
            int h = 4 * w + hj;
            float2 f = *(float2*)&psh[h * LDP + 2 * lane];
            if (l0w + WIN - 1 > idx) {
                int lb = l0w + 2 * lane;
                if (lb     > idx) f.x = -1e30f;
                if (lb + 1 > idx) f.y = -1e30f;
            }
            float tm = fmaxf(f.x, f.y);
            tm = fmaxf(tm, __shfl_xor_sync(0xffffffffu, tm, 16));
            tm = fmaxf(tm, __shfl_xor_sync(0xffffffffu, tm, 8));
            tm = fmaxf(tm, __shfl_xor_sync(0xffffffffu, tm, 4));
            tm = fmaxf(tm, __shfl_xor_sync(0xffffffffu, tm, 2));
            tm = fmaxf(tm, __shfl_xor_sync(0xffffffffu, tm, 1));
            float mn = fmaxf(m_r[hj], tm);
            float co = __expf(m_r[hj] - mn);
            float p0 = __expf(f.x - mn), p1 = __expf(f.y - mn);
            float ls = p0 + p1;
            ls += __shfl_xor_sync(0xffffffffu, ls, 16);
            ls += __shfl_xor_sync(0xffffffffu, ls, 8);
            ls += __shfl_xor_sync(0xffffffffu, ls, 4);
            ls += __shfl_xor_sync(0xffffffffu, ls, 2);
            ls += __shfl_xor_sync(0xffffffffu, ls, 1);
            s_r[hj] = s_r[hj] * co + ls;
            m_r[hj] = mn;

            int half = h >> 4, gp = h & 7, mt = (h >> 3) & 1;
            int kl = lane >> 2;
            int cpos0 = (2 * lane) & 7;       /* even; cpos1 = cpos0+1 */
            int hi4 = cpos0 >> 2;
            int cp0 = cpos0 & 3, cp1 = cp0 + 1;
            int rowbase = (kl * 64 + half * 32 + ((gp + kl) & 7) * 4) * 4
                          + mt + 2 * hi4;
            int sk = (kl >> 1);
            ppkf[rowbase + ((cp0 + sk) & 3) * 4] = tff(p0);
            ppkf[rowbase + ((cp1 + sk) & 3) * 4] = tff(p1);
            if (lane == 0) psh[h * LDP + 64] = co;
        }

        if (wi == 3) cpwait0(); else cpwait1();   /* V_wi ready */
        __syncthreads();            /* probs/corr visible; vbuf stable */
        if (hot) {
            if (t < 128) vbuf[t * LDV + li] += g_v[b * DD + t];
            __syncthreads();
        }

        /* rescale PV accumulators */
        {
            float s0 = psh[(g)      * LDP + 64];
            float s1 = psh[(g + 8)  * LDP + 64];
            float s2 = psh[(g + 16) * LDP + 64];
            float s3 = psh[(g + 24) * LDP + 64];
#pragma unroll
            for (int nt = 0; nt < 2; nt++) {
                acco[0][nt][0] *= s0; acco[0][nt][1] *= s0;
                acco[0][nt][2] *= s1; acco[0][nt][3] *= s1;
                acco[1][nt][0] *= s2; acco[1][nt][1] *= s2;
                acco[1][nt][2] *= s3; acco[1][nt][3] *= s3;
            }
        }

        /* ---- PV: warp w -> d [16w, 16w+16); A from packed probs ---- */
#pragma unroll
        for (int kl = 0; kl < 8; kl++) {
            int pidx = kl * 64 + ((g + kl) & 7) * 4 + ((c + (kl >> 1)) & 3);
            float4 ap0f = ppk4[pidx];
            float4 ap1f = ppk4[pidx + 32];
#pragma unroll
            for (int nt = 0; nt < 2; nt++) {
                int d = w * 16 + nt * 8 + g;
                float v0 = vbuf[d * LDV + kl * 8 + c];
                float v1 = vbuf[d * LDV + kl * 8 + c + 4];
                uint32_t bh[2], bl[2];
                bh[0] = f2tf(v0); bl[0] = f2tf(v0 - __uint_as_float(bh[0]));
                bh[1] = f2tf(v1); bl[1] = f2tf(v1 - __uint_as_float(bh[1]));
                mma8(acco[0][nt], (const uint32_t*)&ap0f, bh);
                mma8(acco[0][nt], (const uint32_t*)&ap0f, bl);
                mma8(acco[1][nt], (const uint32_t*)&ap1f, bh);
                mma8(acco[1][nt], (const uint32_t*)&ap1f, bl);
            }
        }
        __syncthreads();            /* vbuf + psh + ppack free */
        if (wi < 3) fillV(wi + 1);
    }

    /* write partials */
    int pb = (b * NSPLIT + sp) * HH;
    if (lane == 0) {
#pragma unroll
        for (int hj = 0; hj < 4; hj++) {
            g_pm[pb + 4 * w + hj]   = m_r[hj];
            g_psum[pb + 4 * w + hj] = s_r[hj];
        }
    }
#pragma unroll
    for (int mt = 0; mt < 2; mt++)
#pragma unroll
        for (int nt = 0; nt < 2; nt++) {
            int h0 = mt * 16 + g;
            int dd = w * 16 + nt * 8 + 2 * c;
            g_po[(size_t)(pb + h0) * DD + dd]         = acco[mt][nt][0];
            g_po[(size_t)(pb + h0) * DD + dd + 1]     = acco[mt][nt][1];
            g_po[(size_t)(pb + h0 + 8) * DD + dd]     = acco[mt][nt][2];
            g_po[(size_t)(pb + h0 + 8) * DD + dd + 1] = acco[mt][nt][3];
        }
}

/* ---------------- combine (validity-aware) ------------------------------- */
__global__ void combine_kernel(const int* __restrict__ ci) {
    int bh = blockIdx.x;
    int b = bh >> 5, h = bh & 31;
    int d = threadIdx.x;
    int nv = (ci[b] >> 8) + 1;
    float m = -1e30f;
    for (int s = 0; s < nv; s++)
        m = fmaxf(m, g_pm[(b * NSPLIT + s) * HH + h]);
    float S = 0.f, acc = 0.f;
    for (int s = 0; s < nv; s++) {
        int ib = (b * NSPLIT + s) * HH + h;
        float w = __expf(g_pm[ib] - m);
        S   += w * g_psum[ib];
        acc += w * g_po[(size_t)ib * DD + d];
    }
    g_attn[(b * HH + h) * DD + d] = acc / S;
}

/* ---------------- launch ------------------------------------------------- */
extern "C" void kernel_launch(void* const* d_in, const int* in_sizes, int n_in,
                              void* d_out, int out_size) {
    const float* x  = (const float*)d_in[0];
    const float* Kc = (const float*)d_in[1];
    const float* Vc = (const float*)d_in[2];
    const float* Wq = (const float*)d_in[3];
    const float* Wk = (const float*)d_in[4];
    const float* Wv = (const float*)d_in[5];
    const float* Wo = (const float*)d_in[6];
    const int*   ci = (const int*)d_in[7];
    float* out = (float*)d_out;

    float *qp, *ap;
    cudaGetSymbolAddress((void**)&qp, g_q);
    cudaGetSymbolAddress((void**)&ap, g_attn);

    cudaFuncSetAttribute(tgemm32,
                         cudaFuncAttributeMaxDynamicSharedMemorySize, 168960);
    cudaFuncSetAttribute(attn_kernel,
                         cudaFuncAttributeMaxDynamicSharedMemorySize, 104960);

    zero_kernel<<<512, 256>>>(out);
    tgemm32<<<dim3(16, SPLITK), 256, 168960>>>(x, Wq, qp, 4096);
    kvproj<<<dim3(2, 32), 256>>>(x, Wk, Wv);
    attn_kernel<<<dim3(32, NSPLIT), 256, 104960>>>(Kc, Vc, ci);
    combine_kernel<<<1024, 128>>>(ci);
    tgemm32<<<dim3(16, SPLITK), 256, 168960>>>(ap, Wo, out, 4096);
}

// round 11
// speedup vs baseline: 1.1343x; 1.0511x over previous
#include <cuda_runtime.h>
#include <math.h>
#include <stdint.h>

#define BB 32
#define FF 4096
#define HH 32
#define DD 128
#define LL 8192
#define NSPLIT 32
#define CH (LL/NSPLIT)          /* 256 */
#define WIN 64
#define LDW 72                  /* K window stride (floats) */
#define LDV 68                  /* V window stride (floats) */
#define LDP 68                  /* psh row stride (col 64 = corr) */
#define SCALE 0.08838834764831845f

/* ---------------- scratch ------------------------------------------------ */
__device__ float g_q[BB*HH*DD];
__device__ float g_k[BB*DD];
__device__ float g_v[BB*DD];
__device__ float g_attn[BB*HH*DD];
__device__ float g_pm[BB*NSPLIT*HH];
__device__ float g_psum[BB*NSPLIT*HH];
__device__ float g_po[BB*NSPLIT*HH*DD];
__device__ float g_freq[64];

/* ---------------- helpers ------------------------------------------------ */
__device__ __forceinline__ uint32_t s2u(const void* p) {
    return (uint32_t)__cvta_generic_to_shared(p);
}
__device__ __forceinline__ void cpa16(uint32_t s, const void* g) {
    asm volatile("cp.async.cg.shared.global [%0], [%1], 16;" :: "r"(s), "l"(g));
}
__device__ __forceinline__ void cpcommit() { asm volatile("cp.async.commit_group;"); }
__device__ __forceinline__ void cpwait0()  { asm volatile("cp.async.wait_group 0;"); }
__device__ __forceinline__ void cpwait1()  { asm volatile("cp.async.wait_group 1;"); }

__device__ __forceinline__ uint32_t f2tf(float x) {
    uint32_t r; asm("cvt.rna.tf32.f32 %0, %1;" : "=r"(r) : "f"(x)); return r;
}
__device__ __forceinline__ float tff(float x) { return __uint_as_float(f2tf(x)); }
__device__ __forceinline__ void mma8(float* d, const uint32_t* a, const uint32_t* b) {
    asm volatile("mma.sync.aligned.m16n8k8.row.col.f32.tf32.tf32.f32 "
        "{%0,%1,%2,%3},{%4,%5,%6,%7},{%8,%9},{%0,%1,%2,%3};"
        : "+f"(d[0]), "+f"(d[1]), "+f"(d[2]), "+f"(d[3])
        : "r"(a[0]), "r"(a[1]), "r"(a[2]), "r"(a[3]), "r"(b[0]), "r"(b[1]));
}

/* ---------------- zero + freq table -------------------------------------- */
__global__ void zero_kernel(float* __restrict__ out) {
    int i = blockIdx.x * 256 + threadIdx.x;
    g_q[i] = 0.f;
    out[i] = 0.f;
    if (i < BB*DD) { g_k[i] = 0.f; g_v[i] = 0.f; }
    if (i < 64) g_freq[i] = (float)exp(-(double)i * 0.14391156831212787);
}

/* ---------------- tensor GEMM v3 (3xTF32, 2-stage, 2 CTA/SM) --------------
 * C[32,N] += A[32,4096] * W[4096,N]. grid (N/256, 16) = 256 blocks.
 * N-tile 256 (warp covers 32 cols), split-K 16 (KSL=256, 8 kb-steps).
 * smem: As[256][33] | Ws 2 x [32][264] = 101,376 B -> 2 CTAs/SM.          */
#define SPLITK 16
#define KSL (FF/SPLITK)          /* 256 */
__global__ __launch_bounds__(256, 2) void tgemm32(
        const float* __restrict__ A, const float* __restrict__ W,
        float* __restrict__ C, int N) {
    extern __shared__ float sm[];
    float* As = sm;                  /* 8448 floats */
    float* Ws = sm + 8448;           /* 2 x 8448 floats */
    uint32_t ws_u = s2u(Ws);

    int n0 = blockIdx.x * 256;
    int k0 = blockIdx.y * KSL;
    int t = threadIdx.x, wp = t >> 5, lane = t & 31;
    int g = lane >> 2, c = lane & 3;

    /* A slice [32 x 256] -> As[k][m], one-time */
#pragma unroll
    for (int p = 0; p < 32; p++) {
        int i = t + p * 256;
        int m = i >> 8, k = i & 255;
        As[k * 33 + m] = A[m * FF + k0 + k];
    }
    auto loadW = [&](int kb, int buf) {
        const float* src = W + (size_t)(k0 + kb * 32) * N + n0;
#pragma unroll
        for (int p = 0; p < 8; p++) {
            int ci = t + p * 256;
            int kk = ci >> 6, u = ci & 63;
            cpa16(ws_u + (uint32_t)(buf * 8448 + kk * 264 + 4 * u) * 4,
                  src + (size_t)kk * N + 4 * u);
        }
        cpcommit();
    };
    loadW(0, 0);
    loadW(1, 1);

    float acc[2][4][4];
#pragma unroll
    for (int mt = 0; mt < 2; mt++)
#pragma unroll
        for (int nt = 0; nt < 4; nt++)
#pragma unroll
            for (int r = 0; r < 4; r++) acc[mt][nt][r] = 0.f;

    for (int kb = 0; kb < 8; kb++) {
        if (kb == 7) cpwait0(); else cpwait1();
        __syncthreads();
        const float* wsb = Ws + (kb & 1) * 8448;

#pragma unroll
        for (int ks = 0; ks < 4; ks++) {
            int kg = kb * 32 + ks * 8;
            uint32_t ahi[2][4], alo[2][4];
#pragma unroll
            for (int mt = 0; mt < 2; mt++) {
                float a0 = As[(kg + c)     * 33 + mt * 16 + g];
                float a1 = As[(kg + c)     * 33 + mt * 16 + g + 8];
                float a2 = As[(kg + c + 4) * 33 + mt * 16 + g];
                float a3 = As[(kg + c + 4) * 33 + mt * 16 + g + 8];
                ahi[mt][0] = f2tf(a0); alo[mt][0] = f2tf(a0 - __uint_as_float(ahi[mt][0]));
                ahi[mt][1] = f2tf(a1); alo[mt][1] = f2tf(a1 - __uint_as_float(ahi[mt][1]));
                ahi[mt][2] = f2tf(a2); alo[mt][2] = f2tf(a2 - __uint_as_float(ahi[mt][2]));
                ahi[mt][3] = f2tf(a3); alo[mt][3] = f2tf(a3 - __uint_as_float(ahi[mt][3]));
            }
#pragma unroll
            for (int nt = 0; nt < 4; nt++) {
                float b0 = wsb[(ks * 8 + c)     * 264 + wp * 32 + nt * 8 + g];
                float b1 = wsb[(ks * 8 + c + 4) * 264 + wp * 32 + nt * 8 + g];
                uint32_t bhi[2], blo[2];
                bhi[0] = f2tf(b0); blo[0] = f2tf(b0 - __uint_as_float(bhi[0]));
                bhi[1] = f2tf(b1); blo[1] = f2tf(b1 - __uint_as_float(bhi[1]));
#pragma unroll
                for (int mt = 0; mt < 2; mt++) {
                    mma8(acc[mt][nt], ahi[mt], bhi);
                    mma8(acc[mt][nt], ahi[mt], blo);
                    mma8(acc[mt][nt], alo[mt], bhi);
                }
            }
        }
        __syncthreads();              /* done reading buf kb&1 */
        if (kb < 6) loadW(kb + 2, kb & 1);
    }
#pragma unroll
    for (int mt = 0; mt < 2; mt++)
#pragma unroll
        for (int nt = 0; nt < 4; nt++) {
            int row = mt * 16 + g;
            int col = n0 + wp * 32 + nt * 8 + 2 * c;
            atomicAdd(&C[(row)     * N + col],     acc[mt][nt][0]);
            atomicAdd(&C[(row)     * N + col + 1], acc[mt][nt][1]);
            atomicAdd(&C[(row + 8) * N + col],     acc[mt][nt][2]);
            atomicAdd(&C[(row + 8) * N + col + 1], acc[mt][nt][3]);
        }
}

/* ---------------- k/v projection ----------------------------------------- */
__global__ __launch_bounds__(256) void kvproj(
        const float* __restrict__ A, const float* __restrict__ Wk,
        const float* __restrict__ Wv) {
    __shared__ float As[32][36];
    __shared__ float Ws[32][132];
    const float* W = blockIdx.x ? Wv : Wk;
    float* C = blockIdx.x ? g_v : g_k;
    int k0 = blockIdx.y * 128;
    int t = threadIdx.x;
    int mi = t >> 5, ni = t & 31;
    float acc[4][4];
#pragma unroll
    for (int i = 0; i < 4; i++)
#pragma unroll
        for (int j = 0; j < 4; j++) acc[i][j] = 0.f;

    for (int kb = 0; kb < 128; kb += 32) {
        int kg = k0 + kb;
#pragma unroll
        for (int p = 0; p < 4; p++) {
            int i = t + p * 256;
            As[i & 31][i >> 5] = A[(i >> 5) * FF + kg + (i & 31)];
        }
#pragma unroll
        for (int p = 0; p < 4; p++) {
            int i = t + p * 256;
            int kk = i >> 5, nq = i & 31;
            *(float4*)&Ws[kk][nq * 4] = *(const float4*)&W[(kg + kk) * DD + nq * 4];
        }
        __syncthreads();
#pragma unroll
        for (int kk = 0; kk < 32; kk++) {
            float4 a = *(float4*)&As[kk][mi * 4];
            float4 w = *(float4*)&Ws[kk][ni * 4];
            acc[0][0] += a.x*w.x; acc[0][1] += a.x*w.y; acc[0][2] += a.x*w.z; acc[0][3] += a.x*w.w;
            acc[1][0] += a.y*w.x; acc[1][1] += a.y*w.y; acc[1][2] += a.y*w.z; acc[1][3] += a.y*w.w;
            acc[2][0] += a.z*w.x; acc[2][1] += a.z*w.y; acc[2][2] += a.z*w.z; acc[2][3] += a.z*w.w;
            acc[3][0] += a.w*w.x; acc[3][1] += a.w*w.y; acc[3][2] += a.w*w.z; acc[3][3] += a.w*w.w;
        }
        __syncthreads();
    }
#pragma unroll
    for (int i = 0; i < 4; i++)
#pragma unroll
        for (int j = 0; j < 4; j++)
            atomicAdd(&C[(mi * 4 + i) * DD + ni * 4 + j], acc[i][j]);
}

/* ---------------- flash-decode attention v5 (unchanged from R10) ---------- */
__global__ __launch_bounds__(256, 2) void attn_kernel(
        const float* __restrict__ Kc, const float* __restrict__ Vc,
        const int* __restrict__ ci) {
    extern __shared__ float sm[];
    float4* qfh4 = (float4*)sm;                 /* 1024 float4 */
    float*  psh  = sm + 4096;                   /* 2176 */
    float*  ppkf = sm + 6272;                   /* 2048 */
    float4* ppk4 = (float4*)ppkf;
    float*  kbuf = sm + 8320;                   /* 9216 */
    float*  vbuf = sm + 17536;                  /* 8704 */

    int b = blockIdx.x, sp = blockIdx.y;
    int idx = ci[b];
    int c0  = sp * CH;
    if (c0 > idx) return;

    int t = threadIdx.x, w = t >> 5, lane = t & 31;
    int g = lane >> 2, c = lane & 3;
    float pos = (float)idx;

    const float* Kb = Kc + (size_t)b * DD * LL;
    const float* Vb = Vc + (size_t)b * DD * LL;

    auto fillK = [&](int wi) {
        uint32_t dst = s2u(kbuf);
        const float* src = Kb + c0 + wi * WIN;
#pragma unroll
        for (int p = 0; p < 8; p++) {
            int i = t + p * 256; int d = i >> 4, u = i & 15;
            cpa16(dst + (uint32_t)(d * LDW + 4 * u) * 4, src + (size_t)d * LL + 4 * u);
        }
        cpcommit();
    };
    auto fillV = [&](int wi) {
        uint32_t dst = s2u(vbuf);
        const float* src = Vb + c0 + wi * WIN;
#pragma unroll
        for (int p = 0; p < 8; p++) {
            int i = t + p * 256; int d = i >> 4, u = i & 15;
            cpa16(dst + (uint32_t)(d * LDV + 4 * u) * 4, src + (size_t)d * LL + 4 * u);
        }
        cpcommit();
    };

    fillK(0);
    fillV(0);

    /* q -> rope -> scale -> single tf32, swizzled fragment layout */
#pragma unroll
    for (int p = 0; p < 4; p++) {
        int fid = p * 256 + t;
        int kd = fid >> 6, mt = (fid >> 5) & 1, cc = (fid >> 3) & 3, gg = fid & 7;
        int r0 = mt * 16 + gg, r1 = r0 + 8;
        const float* qb = g_q + b * HH * DD;
        float4 hi;
        float e[4];
#pragma unroll
        for (int dj = 0; dj < 2; dj++) {
            int dcol = 8 * kd + cc + 4 * dj;
            float si, co;
            sincosf(pos * g_freq[dcol & 63], &si, &co);
#pragma unroll
            for (int rj = 0; rj < 2; rj++) {
                int r = rj ? r1 : r0;
                float a = qb[r * DD + dcol];
                float o = qb[r * DD + (dcol ^ 64)];
                float v = (dcol < 64) ? (a * co - o * si) : (a * co + o * si);
                e[dj * 2 + rj] = v * SCALE;
            }
        }
        hi.x = tff(e[0]); hi.y = tff(e[1]); hi.z = tff(e[2]); hi.w = tff(e[3]);
        int sfid = kd * 64 + mt * 32 + cc * 8 + ((gg + 2 * cc) & 7);
        qfh4[sfid] = hi;
    }
    __syncthreads();

    int swz = c * 8 + ((g + 2 * c) & 7);

    float m_r[4] = {-1e30f, -1e30f, -1e30f, -1e30f};
    float s_r[4] = {0.f, 0.f, 0.f, 0.f};
    float acco[2][2][4];
#pragma unroll
    for (int mt = 0; mt < 2; mt++)
#pragma unroll
        for (int nt = 0; nt < 2; nt++)
#pragma unroll
            for (int r = 0; r < 4; r++) acco[mt][nt][r] = 0.f;

    for (int wi = 0; wi < 4; wi++) {
        int l0w = c0 + wi * WIN;
        int hot = (idx >= l0w) && (idx < l0w + WIN);
        int li = idx - l0w;

        cpwait1();
        __syncthreads();
        if (hot) {
            if (t < 128) {
                float si, co;
                sincosf(pos * g_freq[t & 63], &si, &co);
                float a = g_k[b * DD + t];
                float o = g_k[b * DD + (t ^ 64)];
                float kr = (t < 64) ? (a * co - o * si) : (a * co + o * si);
                kbuf[t * LDW + li] += kr;
            }
            __syncthreads();
        }

        /* ---- QK ---- */
        float accq[2][4];
#pragma unroll
        for (int mt = 0; mt < 2; mt++)
#pragma unroll
            for (int r = 0; r < 4; r++) accq[mt][r] = 0.f;

#pragma unroll
        for (int kd = 0; kd < 16; kd++) {
            float4 ah0 = qfh4[kd * 64 +      swz];
            float4 ah1 = qfh4[kd * 64 + 32 + swz];
            float b0 = kbuf[(kd * 8 + c)     * LDW + w * 8 + g];
            float b1 = kbuf[(kd * 8 + c + 4) * LDW + w * 8 + g];
            uint32_t bb[2] = {f2tf(b0), f2tf(b1)};
            mma8(accq[0], (const uint32_t*)&ah0, bb);
            mma8(accq[1], (const uint32_t*)&ah1, bb);
        }
#pragma unroll
        for (int mt = 0; mt < 2; mt++) {
            int r0 = mt * 16 + g, cb = w * 8 + 2 * c;
            psh[r0 * LDP + cb]           = accq[mt][0];
            psh[r0 * LDP + cb + 1]       = accq[mt][1];
            psh[(r0 + 8) * LDP + cb]     = accq[mt][2];
            psh[(r0 + 8) * LDP + cb + 1] = accq[mt][3];
        }
        __syncthreads();
        if (wi < 3) fillK(wi + 1);

        /* ---- online softmax; probs stored fragment-packed ---- */
#pragma unroll
        for (int hj = 0; hj < 4; hj++) {
            int h = 4 * w + hj;
            float2 f = *(float2*)&psh[h * LDP + 2 * lane];
            if (l0w + WIN - 1 > idx) {
                int lb = l0w + 2 * lane;
                if (lb     > idx) f.x = -1e30f;
                if (lb + 1 > idx) f.y = -1e30f;
            }
            float tm = fmaxf(f.x, f.y);
            tm = fmaxf(tm, __shfl_xor_sync(0xffffffffu, tm, 16));
            tm = fmaxf(tm, __shfl_xor_sync(0xffffffffu, tm, 8));
            tm = fmaxf(tm, __shfl_xor_sync(0xffffffffu, tm, 4));
            tm = fmaxf(tm, __shfl_xor_sync(0xffffffffu, tm, 2));
            tm = fmaxf(tm, __shfl_xor_sync(0xffffffffu, tm, 1));
            float mn = fmaxf(m_r[hj], tm);
            float co = __expf(m_r[hj] - mn);
            float p0 = __expf(f.x - mn), p1 = __expf(f.y - mn);
            float ls = p0 + p1;
            ls += __shfl_xor_sync(0xffffffffu, ls, 16);
            ls += __shfl_xor_sync(0xffffffffu, ls, 8);
            ls += __shfl_xor_sync(0xffffffffu, ls, 4);
            ls += __shfl_xor_sync(0xffffffffu, ls, 2);
            ls += __shfl_xor_sync(0xffffffffu, ls, 1);
            s_r[hj] = s_r[hj] * co + ls;
            m_r[hj] = mn;

            int half = h >> 4, gp = h & 7, mt = (h >> 3) & 1;
            int kl = lane >> 2;
            int cpos0 = (2 * lane) & 7;
            int hi4 = cpos0 >> 2;
            int cp0 = cpos0 & 3, cp1 = cp0 + 1;
            int rowbase = (kl * 64 + half * 32 + ((gp + kl) & 7) * 4) * 4
                          + mt + 2 * hi4;
            int sk = (kl >> 1);
            ppkf[rowbase + ((cp0 + sk) & 3) * 4] = tff(p0);
            ppkf[rowbase + ((cp1 + sk) & 3) * 4] = tff(p1);
            if (lane == 0) psh[h * LDP + 64] = co;
        }

        if (wi == 3) cpwait0(); else cpwait1();
        __syncthreads();
        if (hot) {
            if (t < 128) vbuf[t * LDV + li] += g_v[b * DD + t];
            __syncthreads();
        }

        /* rescale PV accumulators */
        {
            float s0 = psh[(g)      * LDP + 64];
            float s1 = psh[(g + 8)  * LDP + 64];
            float s2 = psh[(g + 16) * LDP + 64];
            float s3 = psh[(g + 24) * LDP + 64];
#pragma unroll
            for (int nt = 0; nt < 2; nt++) {
                acco[0][nt][0] *= s0; acco[0][nt][1] *= s0;
                acco[0][nt][2] *= s1; acco[0][nt][3] *= s1;
                acco[1][nt][0] *= s2; acco[1][nt][1] *= s2;
                acco[1][nt][2] *= s3; acco[1][nt][3] *= s3;
            }
        }

        /* ---- PV ---- */
#pragma unroll
        for (int kl = 0; kl < 8; kl++) {
            int pidx = kl * 64 + ((g + kl) & 7) * 4 + ((c + (kl >> 1)) & 3);
            float4 ap0f = ppk4[pidx];
            float4 ap1f = ppk4[pidx + 32];
#pragma unroll
            for (int nt = 0; nt < 2; nt++) {
                int d = w * 16 + nt * 8 + g;
                float v0 = vbuf[d * LDV + kl * 8 + c];
                float v1 = vbuf[d * LDV + kl * 8 + c + 4];
                uint32_t bh[2], bl[2];
                bh[0] = f2tf(v0); bl[0] = f2tf(v0 - __uint_as_float(bh[0]));
                bh[1] = f2tf(v1); bl[1] = f2tf(v1 - __uint_as_float(bh[1]));
                mma8(acco[0][nt], (const uint32_t*)&ap0f, bh);
                mma8(acco[0][nt], (const uint32_t*)&ap0f, bl);
                mma8(acco[1][nt], (const uint32_t*)&ap1f, bh);
                mma8(acco[1][nt], (const uint32_t*)&ap1f, bl);
            }
        }
        __syncthreads();
        if (wi < 3) fillV(wi + 1);
    }

    /* write partials */
    int pb = (b * NSPLIT + sp) * HH;
    if (lane == 0) {
#pragma unroll
        for (int hj = 0; hj < 4; hj++) {
            g_pm[pb + 4 * w + hj]   = m_r[hj];
            g_psum[pb + 4 * w + hj] = s_r[hj];
        }
    }
#pragma unroll
    for (int mt = 0; mt < 2; mt++)
#pragma unroll
        for (int nt = 0; nt < 2; nt++) {
            int h0 = mt * 16 + g;
            int dd = w * 16 + nt * 8 + 2 * c;
            g_po[(size_t)(pb + h0) * DD + dd]         = acco[mt][nt][0];
            g_po[(size_t)(pb + h0) * DD + dd + 1]     = acco[mt][nt][1];
            g_po[(size_t)(pb + h0 + 8) * DD + dd]     = acco[mt][nt][2];
            g_po[(size_t)(pb + h0 + 8) * DD + dd + 1] = acco[mt][nt][3];
        }
}

/* ---------------- combine (validity-aware) ------------------------------- */
__global__ void combine_kernel(const int* __restrict__ ci) {
    int bh = blockIdx.x;
    int b = bh >> 5, h = bh & 31;
    int d = threadIdx.x;
    int nv = (ci[b] >> 8) + 1;
    float m = -1e30f;
    for (int s = 0; s < nv; s++)
        m = fmaxf(m, g_pm[(b * NSPLIT + s) * HH + h]);
    float S = 0.f, acc = 0.f;
    for (int s = 0; s < nv; s++) {
        int ib = (b * NSPLIT + s) * HH + h;
        float w = __expf(g_pm[ib] - m);
        S   += w * g_psum[ib];
        acc += w * g_po[(size_t)ib * DD + d];
    }
    g_attn[(b * HH + h) * DD + d] = acc / S;
}

/* ---------------- launch ------------------------------------------------- */
extern "C" void kernel_launch(void* const* d_in, const int* in_sizes, int n_in,
                              void* d_out, int out_size) {
    const float* x  = (const float*)d_in[0];
    const float* Kc = (const float*)d_in[1];
    const float* Vc = (const float*)d_in[2];
    const float* Wq = (const float*)d_in[3];
    const float* Wk = (const float*)d_in[4];
    const float* Wv = (const float*)d_in[5];
    const float* Wo = (const float*)d_in[6];
    const int*   ci = (const int*)d_in[7];
    float* out = (float*)d_out;

    float *qp, *ap;
    cudaGetSymbolAddress((void**)&qp, g_q);
    cudaGetSymbolAddress((void**)&ap, g_attn);

    cudaFuncSetAttribute(tgemm32,
                         cudaFuncAttributeMaxDynamicSharedMemorySize, 101376);
    cudaFuncSetAttribute(attn_kernel,
                         cudaFuncAttributeMaxDynamicSharedMemorySize, 104960);

    zero_kernel<<<512, 256>>>(out);
    tgemm32<<<dim3(16, SPLITK), 256, 101376>>>(x, Wq, qp, 4096);
    kvproj<<<dim3(2, 32), 256>>>(x, Wk, Wv);
    attn_kernel<<<dim3(32, NSPLIT), 256, 104960>>>(Kc, Vc, ci);
    combine_kernel<<<1024, 128>>>(ci);
    tgemm32<<<dim3(16, SPLITK), 256, 101376>>>(ap, Wo, out, 4096);
}

// round 12
// speedup vs baseline: 1.2825x; 1.1307x over previous
#include <cuda_runtime.h>
#include <math.h>
#include <stdint.h>

#define BB 32
#define FF 4096
#define HH 32
#define DD 128
#define LL 8192
#define NSPLIT 32
#define CH (LL/NSPLIT)          /* 256 */
#define WIN 64
#define LDW 72                  /* K window stride (floats) */
#define LDV 68                  /* V window stride (floats) */
#define LDP 68                  /* psh row stride (col 64 = corr) */
#define SCALE 0.08838834764831845f

/* ---------------- scratch ------------------------------------------------ */
__device__ float g_q[BB*HH*DD];
__device__ float g_k[BB*DD];
__device__ float g_v[BB*DD];
__device__ float g_attn[BB*HH*DD];
__device__ float g_pm[BB*NSPLIT*HH];
__device__ float g_psum[BB*NSPLIT*HH];
__device__ float g_po[BB*NSPLIT*HH*DD];
__device__ float g_freq[64];

/* ---------------- helpers ------------------------------------------------ */
__device__ __forceinline__ uint32_t s2u(const void* p) {
    return (uint32_t)__cvta_generic_to_shared(p);
}
__device__ __forceinline__ void cpa16(uint32_t s, const void* g) {
    asm volatile("cp.async.cg.shared.global [%0], [%1], 16;" :: "r"(s), "l"(g));
}
__device__ __forceinline__ void cpcommit() { asm volatile("cp.async.commit_group;"); }
__device__ __forceinline__ void cpwait0()  { asm volatile("cp.async.wait_group 0;"); }
__device__ __forceinline__ void cpwait1()  { asm volatile("cp.async.wait_group 1;"); }

__device__ __forceinline__ uint32_t f2tf(float x) {
    uint32_t r; asm("cvt.rna.tf32.f32 %0, %1;" : "=r"(r) : "f"(x)); return r;
}
__device__ __forceinline__ float tff(float x) { return __uint_as_float(f2tf(x)); }
__device__ __forceinline__ void mma8(float* d, const uint32_t* a, const uint32_t* b) {
    asm volatile("mma.sync.aligned.m16n8k8.row.col.f32.tf32.tf32.f32 "
        "{%0,%1,%2,%3},{%4,%5,%6,%7},{%8,%9},{%0,%1,%2,%3};"
        : "+f"(d[0]), "+f"(d[1]), "+f"(d[2]), "+f"(d[3])
        : "r"(a[0]), "r"(a[1]), "r"(a[2]), "r"(a[3]), "r"(b[0]), "r"(b[1]));
}

/* ---------------- zero + freq table -------------------------------------- */
__global__ void zero_kernel(float* __restrict__ out) {
    int i = blockIdx.x * 256 + threadIdx.x;
    g_q[i] = 0.f;
    out[i] = 0.f;
    if (i < BB*DD) { g_k[i] = 0.f; g_v[i] = 0.f; }
    if (i < 64) g_freq[i] = (float)exp(-(double)i * 0.14391156831212787);
}

/* ---------------- tensor GEMM v4: 2-term A x single-term W -----------------
 * C[32,N] += A[32,4096] * W[4096,N]. grid (N/256, 16) = 256 blocks.
 * smem: As[256][33] | Ws 2 x [32][264] = 101,376 B -> 2 CTAs/SM.          */
#define SPLITK 16
#define KSL (FF/SPLITK)          /* 256 */
__global__ __launch_bounds__(256, 2) void tgemm32(
        const float* __restrict__ A, const float* __restrict__ W,
        float* __restrict__ C, int N) {
    extern __shared__ float sm[];
    float* As = sm;                  /* 8448 floats */
    float* Ws = sm + 8448;           /* 2 x 8448 floats */
    uint32_t ws_u = s2u(Ws);

    int n0 = blockIdx.x * 256;
    int k0 = blockIdx.y * KSL;
    int t = threadIdx.x, wp = t >> 5, lane = t & 31;
    int g = lane >> 2, c = lane & 3;

#pragma unroll
    for (int p = 0; p < 32; p++) {
        int i = t + p * 256;
        int m = i >> 8, k = i & 255;
        As[k * 33 + m] = A[m * FF + k0 + k];
    }
    auto loadW = [&](int kb, int buf) {
        const float* src = W + (size_t)(k0 + kb * 32) * N + n0;
#pragma unroll
        for (int p = 0; p < 8; p++) {
            int ci = t + p * 256;
            int kk = ci >> 6, u = ci & 63;
            cpa16(ws_u + (uint32_t)(buf * 8448 + kk * 264 + 4 * u) * 4,
                  src + (size_t)kk * N + 4 * u);
        }
        cpcommit();
    };
    loadW(0, 0);
    loadW(1, 1);

    float acc[2][4][4];
#pragma unroll
    for (int mt = 0; mt < 2; mt++)
#pragma unroll
        for (int nt = 0; nt < 4; nt++)
#pragma unroll
            for (int r = 0; r < 4; r++) acc[mt][nt][r] = 0.f;

    for (int kb = 0; kb < 8; kb++) {
        if (kb == 7) cpwait0(); else cpwait1();
        __syncthreads();
        const float* wsb = Ws + (kb & 1) * 8448;

#pragma unroll
        for (int ks = 0; ks < 4; ks++) {
            int kg = kb * 32 + ks * 8;
            uint32_t ahi[2][4], alo[2][4];
#pragma unroll
            for (int mt = 0; mt < 2; mt++) {
                float a0 = As[(kg + c)     * 33 + mt * 16 + g];
                float a1 = As[(kg + c)     * 33 + mt * 16 + g + 8];
                float a2 = As[(kg + c + 4) * 33 + mt * 16 + g];
                float a3 = As[(kg + c + 4) * 33 + mt * 16 + g + 8];
                ahi[mt][0] = f2tf(a0); alo[mt][0] = f2tf(a0 - __uint_as_float(ahi[mt][0]));
                ahi[mt][1] = f2tf(a1); alo[mt][1] = f2tf(a1 - __uint_as_float(ahi[mt][1]));
                ahi[mt][2] = f2tf(a2); alo[mt][2] = f2tf(a2 - __uint_as_float(ahi[mt][2]));
                ahi[mt][3] = f2tf(a3); alo[mt][3] = f2tf(a3 - __uint_as_float(ahi[mt][3]));
            }
#pragma unroll
            for (int nt = 0; nt < 4; nt++) {
                float b0 = wsb[(ks * 8 + c)     * 264 + wp * 32 + nt * 8 + g];
                float b1 = wsb[(ks * 8 + c + 4) * 264 + wp * 32 + nt * 8 + g];
                uint32_t bhi[2] = {f2tf(b0), f2tf(b1)};
#pragma unroll
                for (int mt = 0; mt < 2; mt++) {
                    mma8(acc[mt][nt], ahi[mt], bhi);
                    mma8(acc[mt][nt], alo[mt], bhi);
                }
            }
        }
        __syncthreads();
        if (kb < 6) loadW(kb + 2, kb & 1);
    }
#pragma unroll
    for (int mt = 0; mt < 2; mt++)
#pragma unroll
        for (int nt = 0; nt < 4; nt++) {
            int row = mt * 16 + g;
            int col = n0 + wp * 32 + nt * 8 + 2 * c;
            atomicAdd(&C[(row)     * N + col],     acc[mt][nt][0]);
            atomicAdd(&C[(row)     * N + col + 1], acc[mt][nt][1]);
            atomicAdd(&C[(row + 8) * N + col],     acc[mt][nt][2]);
            atomicAdd(&C[(row + 8) * N + col + 1], acc[mt][nt][3]);
        }
}

/* ---------------- k/v projection (fp32 FFMA — precision anchor) ----------- */
__global__ __launch_bounds__(256) void kvproj(
        const float* __restrict__ A, const float* __restrict__ Wk,
        const float* __restrict__ Wv) {
    __shared__ float As[32][36];
    __shared__ float Ws[32][132];
    const float* W = blockIdx.x ? Wv : Wk;
    float* C = blockIdx.x ? g_v : g_k;
    int k0 = blockIdx.y * 128;
    int t = threadIdx.x;
    int mi = t >> 5, ni = t & 31;
    float acc[4][4];
#pragma unroll
    for (int i = 0; i < 4; i++)
#pragma unroll
        for (int j = 0; j < 4; j++) acc[i][j] = 0.f;

    for (int kb = 0; kb < 128; kb += 32) {
        int kg = k0 + kb;
#pragma unroll
        for (int p = 0; p < 4; p++) {
            int i = t + p * 256;
            As[i & 31][i >> 5] = A[(i >> 5) * FF + kg + (i & 31)];
        }
#pragma unroll
        for (int p = 0; p < 4; p++) {
            int i = t + p * 256;
            int kk = i >> 5, nq = i & 31;
            *(float4*)&Ws[kk][nq * 4] = *(const float4*)&W[(kg + kk) * DD + nq * 4];
        }
        __syncthreads();
#pragma unroll
        for (int kk = 0; kk < 32; kk++) {
            float4 a = *(float4*)&As[kk][mi * 4];
            float4 w = *(float4*)&Ws[kk][ni * 4];
            acc[0][0] += a.x*w.x; acc[0][1] += a.x*w.y; acc[0][2] += a.x*w.z; acc[0][3] += a.x*w.w;
            acc[1][0] += a.y*w.x; acc[1][1] += a.y*w.y; acc[1][2] += a.y*w.z; acc[1][3] += a.y*w.w;
            acc[2][0] += a.z*w.x; acc[2][1] += a.z*w.y; acc[2][2] += a.z*w.z; acc[2][3] += a.z*w.w;
            acc[3][0] += a.w*w.x; acc[3][1] += a.w*w.y; acc[3][2] += a.w*w.z; acc[3][3] += a.w*w.w;
        }
        __syncthreads();
    }
#pragma unroll
    for (int i = 0; i < 4; i++)
#pragma unroll
        for (int j = 0; j < 4; j++)
            atomicAdd(&C[(mi * 4 + i) * DD + ni * 4 + j], acc[i][j]);
}

/* ---------------- flash-decode attention v6: single-term V in PV ---------- */
__global__ __launch_bounds__(256, 2) void attn_kernel(
        const float* __restrict__ Kc, const float* __restrict__ Vc,
        const int* __restrict__ ci) {
    extern __shared__ float sm[];
    float4* qfh4 = (float4*)sm;                 /* 1024 float4 */
    float*  psh  = sm + 4096;                   /* 2176 */
    float*  ppkf = sm + 6272;                   /* 2048 */
    float4* ppk4 = (float4*)ppkf;
    float*  kbuf = sm + 8320;                   /* 9216 */
    float*  vbuf = sm + 17536;                  /* 8704 */

    int b = blockIdx.x, sp = blockIdx.y;
    int idx = ci[b];
    int c0  = sp * CH;
    if (c0 > idx) return;

    int t = threadIdx.x, w = t >> 5, lane = t & 31;
    int g = lane >> 2, c = lane & 3;
    float pos = (float)idx;

    const float* Kb = Kc + (size_t)b * DD * LL;
    const float* Vb = Vc + (size_t)b * DD * LL;

    auto fillK = [&](int wi) {
        uint32_t dst = s2u(kbuf);
        const float* src = Kb + c0 + wi * WIN;
#pragma unroll
        for (int p = 0; p < 8; p++) {
            int i = t + p * 256; int d = i >> 4, u = i & 15;
            cpa16(dst + (uint32_t)(d * LDW + 4 * u) * 4, src + (size_t)d * LL + 4 * u);
        }
        cpcommit();
    };
    auto fillV = [&](int wi) {
        uint32_t dst = s2u(vbuf);
        const float* src = Vb + c0 + wi * WIN;
#pragma unroll
        for (int p = 0; p < 8; p++) {
            int i = t + p * 256; int d = i >> 4, u = i & 15;
            cpa16(dst + (uint32_t)(d * LDV + 4 * u) * 4, src + (size_t)d * LL + 4 * u);
        }
        cpcommit();
    };

    fillK(0);
    fillV(0);

    /* q -> rope -> scale -> single tf32, swizzled fragment layout */
#pragma unroll
    for (int p = 0; p < 4; p++) {
        int fid = p * 256 + t;
        int kd = fid >> 6, mt = (fid >> 5) & 1, cc = (fid >> 3) & 3, gg = fid & 7;
        int r0 = mt * 16 + gg, r1 = r0 + 8;
        const float* qb = g_q + b * HH * DD;
        float4 hi;
        float e[4];
#pragma unroll
        for (int dj = 0; dj < 2; dj++) {
            int dcol = 8 * kd + cc + 4 * dj;
            float si, co;
            sincosf(pos * g_freq[dcol & 63], &si, &co);
#pragma unroll
            for (int rj = 0; rj < 2; rj++) {
                int r = rj ? r1 : r0;
                float a = qb[r * DD + dcol];
                float o = qb[r * DD + (dcol ^ 64)];
                float v = (dcol < 64) ? (a * co - o * si) : (a * co + o * si);
                e[dj * 2 + rj] = v * SCALE;
            }
        }
        hi.x = tff(e[0]); hi.y = tff(e[1]); hi.z = tff(e[2]); hi.w = tff(e[3]);
        int sfid = kd * 64 + mt * 32 + cc * 8 + ((gg + 2 * cc) & 7);
        qfh4[sfid] = hi;
    }
    __syncthreads();

    int swz = c * 8 + ((g + 2 * c) & 7);

    float m_r[4] = {-1e30f, -1e30f, -1e30f, -1e30f};
    float s_r[4] = {0.f, 0.f, 0.f, 0.f};
    float acco[2][2][4];
#pragma unroll
    for (int mt = 0; mt < 2; mt++)
#pragma unroll
        for (int nt = 0; nt < 2; nt++)
#pragma unroll
            for (int r = 0; r < 4; r++) acco[mt][nt][r] = 0.f;

    for (int wi = 0; wi < 4; wi++) {
        int l0w = c0 + wi * WIN;
        int hot = (idx >= l0w) && (idx < l0w + WIN);
        int li = idx - l0w;

        cpwait1();
        __syncthreads();
        if (hot) {
            if (t < 128) {
                float si, co;
                sincosf(pos * g_freq[t & 63], &si, &co);
                float a = g_k[b * DD + t];
                float o = g_k[b * DD + (t ^ 64)];
                float kr = (t < 64) ? (a * co - o * si) : (a * co + o * si);
                kbuf[t * LDW + li] += kr;
            }
            __syncthreads();
        }

        /* ---- QK ---- */
        float accq[2][4];
#pragma unroll
        for (int mt = 0; mt < 2; mt++)
#pragma unroll
            for (int r = 0; r < 4; r++) accq[mt][r] = 0.f;

#pragma unroll
        for (int kd = 0; kd < 16; kd++) {
            float4 ah0 = qfh4[kd * 64 +      swz];
            float4 ah1 = qfh4[kd * 64 + 32 + swz];
            float b0 = kbuf[(kd * 8 + c)     * LDW + w * 8 + g];
            float b1 = kbuf[(kd * 8 + c + 4) * LDW + w * 8 + g];
            uint32_t bb[2] = {f2tf(b0), f2tf(b1)};
            mma8(accq[0], (const uint32_t*)&ah0, bb);
            mma8(accq[1], (const uint32_t*)&ah1, bb);
        }
#pragma unroll
        for (int mt = 0; mt < 2; mt++) {
            int r0 = mt * 16 + g, cb = w * 8 + 2 * c;
            psh[r0 * LDP + cb]           = accq[mt][0];
            psh[r0 * LDP + cb + 1]       = accq[mt][1];
            psh[(r0 + 8) * LDP + cb]     = accq[mt][2];
            psh[(r0 + 8) * LDP + cb + 1] = accq[mt][3];
        }
        __syncthreads();
        if (wi < 3) fillK(wi + 1);

        /* ---- online softmax; probs stored fragment-packed ---- */
#pragma unroll
        for (int hj = 0; hj < 4; hj++) {
            int h = 4 * w + hj;
            float2 f = *(float2*)&psh[h * LDP + 2 * lane];
            if (l0w + WIN - 1 > idx) {
                int lb = l0w + 2 * lane;
                if (lb     > idx) f.x = -1e30f;
                if (lb + 1 > idx) f.y = -1e30f;
            }
            float tm = fmaxf(f.x, f.y);
            tm = fmaxf(tm, __shfl_xor_sync(0xffffffffu, tm, 16));
            tm = fmaxf(tm, __shfl_xor_sync(0xffffffffu, tm, 8));
            tm = fmaxf(tm, __shfl_xor_sync(0xffffffffu, tm, 4));
            tm = fmaxf(tm, __shfl_xor_sync(0xffffffffu, tm, 2));
            tm = fmaxf(tm, __shfl_xor_sync(0xffffffffu, tm, 1));
            float mn = fmaxf(m_r[hj], tm);
            float co = __expf(m_r[hj] - mn);
            float p0 = __expf(f.x - mn), p1 = __expf(f.y - mn);
            float ls = p0 + p1;
            ls += __shfl_xor_sync(0xffffffffu, ls, 16);
            ls += __shfl_xor_sync(0xffffffffu, ls, 8);
            ls += __shfl_xor_sync(0xffffffffu, ls, 4);
            ls += __shfl_xor_sync(0xffffffffu, ls, 2);
            ls += __shfl_xor_sync(0xffffffffu, ls, 1);
            s_r[hj] = s_r[hj] * co + ls;
            m_r[hj] = mn;

            int half = h >> 4, gp = h & 7, mt = (h >> 3) & 1;
            int kl = lane >> 2;
            int cpos0 = (2 * lane) & 7;
            int hi4 = cpos0 >> 2;
            int cp0 = cpos0 & 3, cp1 = cp0 + 1;
            int rowbase = (kl * 64 + half * 32 + ((gp + kl) & 7) * 4) * 4
                          + mt + 2 * hi4;
            int sk = (kl >> 1);
            ppkf[rowbase + ((cp0 + sk) & 3) * 4] = tff(p0);
            ppkf[rowbase + ((cp1 + sk) & 3) * 4] = tff(p1);
            if (lane == 0) psh[h * LDP + 64] = co;
        }

        if (wi == 3) cpwait0(); else cpwait1();
        __syncthreads();
        if (hot) {
            if (t < 128) vbuf[t * LDV + li] += g_v[b * DD + t];
            __syncthreads();
        }

        /* rescale PV accumulators */
        {
            float s0 = psh[(g)      * LDP + 64];
            float s1 = psh[(g + 8)  * LDP + 64];
            float s2 = psh[(g + 16) * LDP + 64];
            float s3 = psh[(g + 24) * LDP + 64];
#pragma unroll
            for (int nt = 0; nt < 2; nt++) {
                acco[0][nt][0] *= s0; acco[0][nt][1] *= s0;
                acco[0][nt][2] *= s1; acco[0][nt][3] *= s1;
                acco[1][nt][0] *= s2; acco[1][nt][1] *= s2;
                acco[1][nt][2] *= s3; acco[1][nt][3] *= s3;
            }
        }

        /* ---- PV: single-term tf32 V ---- */
#pragma unroll
        for (int kl = 0; kl < 8; kl++) {
            int pidx = kl * 64 + ((g + kl) & 7) * 4 + ((c + (kl >> 1)) & 3);
            float4 ap0f = ppk4[pidx];
            float4 ap1f = ppk4[pidx + 32];
#pragma unroll
            for (int nt = 0; nt < 2; nt++) {
                int d = w * 16 + nt * 8 + g;
                float v0 = vbuf[d * LDV + kl * 8 + c];
                float v1 = vbuf[d * LDV + kl * 8 + c + 4];
                uint32_t bh[2] = {f2tf(v0), f2tf(v1)};
                mma8(acco[0][nt], (const uint32_t*)&ap0f, bh);
                mma8(acco[1][nt], (const uint32_t*)&ap1f, bh);
            }
        }
        __syncthreads();
        if (wi < 3) fillV(wi + 1);
    }

    /* write partials */
    int pb = (b * NSPLIT + sp) * HH;
    if (lane == 0) {
#pragma unroll
        for (int hj = 0; hj < 4; hj++) {
            g_pm[pb + 4 * w + hj]   = m_r[hj];
            g_psum[pb + 4 * w + hj] = s_r[hj];
        }
    }
#pragma unroll
    for (int mt = 0; mt < 2; mt++)
#pragma unroll
        for (int nt = 0; nt < 2; nt++) {
            int h0 = mt * 16 + g;
            int dd = w * 16 + nt * 8 + 2 * c;
            g_po[(size_t)(pb + h0) * DD + dd]         = acco[mt][nt][0];
            g_po[(size_t)(pb + h0) * DD + dd + 1]     = acco[mt][nt][1];
            g_po[(size_t)(pb + h0 + 8) * DD + dd]     = acco[mt][nt][2];
            g_po[(size_t)(pb + h0 + 8) * DD + dd + 1] = acco[mt][nt][3];
        }
}

/* ---------------- combine (validity-aware) ------------------------------- */
__global__ void combine_kernel(const int* __restrict__ ci) {
    int bh = blockIdx.x;
    int b = bh >> 5, h = bh & 31;
    int d = threadIdx.x;
    int nv = (ci[b] >> 8) + 1;
    float m = -1e30f;
    for (int s = 0; s < nv; s++)
        m = fmaxf(m, g_pm[(b * NSPLIT + s) * HH + h]);
    float S = 0.f, acc = 0.f;
    for (int s = 0; s < nv; s++) {
        int ib = (b * NSPLIT + s) * HH + h;
        float w = __expf(g_pm[ib] - m);
        S   += w * g_psum[ib];
        acc += w * g_po[(size_t)ib * DD + d];
    }
    g_attn[(b * HH + h) * DD + d] = acc / S;
}

/* ---------------- launch ------------------------------------------------- */
extern "C" void kernel_launch(void* const* d_in, const int* in_sizes, int n_in,
                              void* d_out, int out_size) {
    const float* x  = (const float*)d_in[0];
    const float* Kc = (const float*)d_in[1];
    const float* Vc = (const float*)d_in[2];
    const float* Wq = (const float*)d_in[3];
    const float* Wk = (const float*)d_in[4];
    const float* Wv = (const float*)d_in[5];
    const float* Wo = (const float*)d_in[6];
    const int*   ci = (const int*)d_in[7];
    float* out = (float*)d_out;

    float *qp, *ap;
    cudaGetSymbolAddress((void**)&qp, g_q);
    cudaGetSymbolAddress((void**)&ap, g_attn);

    cudaFuncSetAttribute(tgemm32,
                         cudaFuncAttributeMaxDynamicSharedMemorySize, 101376);
    cudaFuncSetAttribute(attn_kernel,
                         cudaFuncAttributeMaxDynamicSharedMemorySize, 104960);

    zero_kernel<<<512, 256>>>(out);
    tgemm32<<<dim3(16, SPLITK), 256, 101376>>>(x, Wq, qp, 4096);
    kvproj<<<dim3(2, 32), 256>>>(x, Wk, Wv);
    attn_kernel<<<dim3(32, NSPLIT), 256, 104960>>>(Kc, Vc, ci);
    combine_kernel<<<1024, 128>>>(ci);
    tgemm32<<<dim3(16, SPLITK), 256, 101376>>>(ap, Wo, out, 4096);
}

// round 13
// speedup vs baseline: 1.3309x; 1.0378x over previous
#include <cuda_runtime.h>
#include <math.h>
#include <stdint.h>

#define BB 32
#define FF 4096
#define HH 32
#define DD 128
#define LL 8192
#define NSPLIT 32
#define CH (LL/NSPLIT)          /* 256 */
#define WIN 64
#define LDW 72                  /* K window stride (floats) */
#define LDV 68                  /* V window stride (floats) */
#define LDP 68                  /* psh row stride (col 64 = corr) */
#define SCALE 0.08838834764831845f

/* ---------------- scratch ------------------------------------------------ */
__device__ float g_q[BB*HH*DD];
__device__ float g_qf[BB*HH*DD];    /* packed tf32 q fragments */
__device__ float g_k[BB*DD];
__device__ float g_v[BB*DD];
__device__ float g_attn[BB*HH*DD];
__device__ float g_pm[BB*NSPLIT*HH];
__device__ float g_psum[BB*NSPLIT*HH];
__device__ float g_po[BB*NSPLIT*HH*DD];
__device__ float g_freq[64];

/* ---------------- helpers ------------------------------------------------ */
__device__ __forceinline__ uint32_t s2u(const void* p) {
    return (uint32_t)__cvta_generic_to_shared(p);
}
__device__ __forceinline__ void cpa16(uint32_t s, const void* g) {
    asm volatile("cp.async.cg.shared.global [%0], [%1], 16;" :: "r"(s), "l"(g));
}
__device__ __forceinline__ void cpcommit() { asm volatile("cp.async.commit_group;"); }
__device__ __forceinline__ void cpwait0()  { asm volatile("cp.async.wait_group 0;"); }
__device__ __forceinline__ void cpwait1()  { asm volatile("cp.async.wait_group 1;"); }

__device__ __forceinline__ uint32_t f2tf(float x) {
    uint32_t r; asm("cvt.rna.tf32.f32 %0, %1;" : "=r"(r) : "f"(x)); return r;
}
__device__ __forceinline__ float tff(float x) { return __uint_as_float(f2tf(x)); }
__device__ __forceinline__ void mma8(float* d, const uint32_t* a, const uint32_t* b) {
    asm volatile("mma.sync.aligned.m16n8k8.row.col.f32.tf32.tf32.f32 "
        "{%0,%1,%2,%3},{%4,%5,%6,%7},{%8,%9},{%0,%1,%2,%3};"
        : "+f"(d[0]), "+f"(d[1]), "+f"(d[2]), "+f"(d[3])
        : "r"(a[0]), "r"(a[1]), "r"(a[2]), "r"(a[3]), "r"(b[0]), "r"(b[1]));
}

/* ---------------- zero + freq table -------------------------------------- */
__global__ void zero_kernel(float* __restrict__ out) {
    int i = blockIdx.x * 256 + threadIdx.x;
    g_q[i] = 0.f;
    out[i] = 0.f;
    if (i < BB*DD) { g_k[i] = 0.f; g_v[i] = 0.f; }
    if (i < 64) g_freq[i] = (float)exp(-(double)i * 0.14391156831212787);
}

/* ---------------- tensor GEMM v5: A 2-term (TWOA) or single x W single ----- */
#define SPLITK 16
#define KSL (FF/SPLITK)          /* 256 */
template<bool TWOA>
__global__ __launch_bounds__(256, 2) void tgemm32(
        const float* __restrict__ A, const float* __restrict__ W,
        float* __restrict__ C, int N) {
    extern __shared__ float sm[];
    float* As = sm;                  /* 8448 floats */
    float* Ws = sm + 8448;           /* 2 x 8448 floats */
    uint32_t ws_u = s2u(Ws);

    int n0 = blockIdx.x * 256;
    int k0 = blockIdx.y * KSL;
    int t = threadIdx.x, wp = t >> 5, lane = t & 31;
    int g = lane >> 2, c = lane & 3;

#pragma unroll
    for (int p = 0; p < 32; p++) {
        int i = t + p * 256;
        int m = i >> 8, k = i & 255;
        As[k * 33 + m] = A[m * FF + k0 + k];
    }
    auto loadW = [&](int kb, int buf) {
        const float* src = W + (size_t)(k0 + kb * 32) * N + n0;
#pragma unroll
        for (int p = 0; p < 8; p++) {
            int ci = t + p * 256;
            int kk = ci >> 6, u = ci & 63;
            cpa16(ws_u + (uint32_t)(buf * 8448 + kk * 264 + 4 * u) * 4,
                  src + (size_t)kk * N + 4 * u);
        }
        cpcommit();
    };
    loadW(0, 0);
    loadW(1, 1);

    float acc[2][4][4];
#pragma unroll
    for (int mt = 0; mt < 2; mt++)
#pragma unroll
        for (int nt = 0; nt < 4; nt++)
#pragma unroll
            for (int r = 0; r < 4; r++) acc[mt][nt][r] = 0.f;

    for (int kb = 0; kb < 8; kb++) {
        if (kb == 7) cpwait0(); else cpwait1();
        __syncthreads();
        const float* wsb = Ws + (kb & 1) * 8448;

#pragma unroll
        for (int ks = 0; ks < 4; ks++) {
            int kg = kb * 32 + ks * 8;
            uint32_t ahi[2][4], alo[2][4];
#pragma unroll
            for (int mt = 0; mt < 2; mt++) {
                float a0 = As[(kg + c)     * 33 + mt * 16 + g];
                float a1 = As[(kg + c)     * 33 + mt * 16 + g + 8];
                float a2 = As[(kg + c + 4) * 33 + mt * 16 + g];
                float a3 = As[(kg + c + 4) * 33 + mt * 16 + g + 8];
                ahi[mt][0] = f2tf(a0);
                ahi[mt][1] = f2tf(a1);
                ahi[mt][2] = f2tf(a2);
                ahi[mt][3] = f2tf(a3);
                if (TWOA) {
                    alo[mt][0] = f2tf(a0 - __uint_as_float(ahi[mt][0]));
                    alo[mt][1] = f2tf(a1 - __uint_as_float(ahi[mt][1]));
                    alo[mt][2] = f2tf(a2 - __uint_as_float(ahi[mt][2]));
                    alo[mt][3] = f2tf(a3 - __uint_as_float(ahi[mt][3]));
                }
            }
#pragma unroll
            for (int nt = 0; nt < 4; nt++) {
                float b0 = wsb[(ks * 8 + c)     * 264 + wp * 32 + nt * 8 + g];
                float b1 = wsb[(ks * 8 + c + 4) * 264 + wp * 32 + nt * 8 + g];
                uint32_t bhi[2] = {f2tf(b0), f2tf(b1)};
#pragma unroll
                for (int mt = 0; mt < 2; mt++) {
                    mma8(acc[mt][nt], ahi[mt], bhi);
                    if (TWOA) mma8(acc[mt][nt], alo[mt], bhi);
                }
            }
        }
        __syncthreads();
        if (kb < 6) loadW(kb + 2, kb & 1);
    }
#pragma unroll
    for (int mt = 0; mt < 2; mt++)
#pragma unroll
        for (int nt = 0; nt < 4; nt++) {
            int row = mt * 16 + g;
            int col = n0 + wp * 32 + nt * 8 + 2 * c;
            atomicAdd(&C[(row)     * N + col],     acc[mt][nt][0]);
            atomicAdd(&C[(row)     * N + col + 1], acc[mt][nt][1]);
            atomicAdd(&C[(row + 8) * N + col],     acc[mt][nt][2]);
            atomicAdd(&C[(row + 8) * N + col + 1], acc[mt][nt][3]);
        }
}

/* ---------------- k/v projection (fp32 FFMA — precision anchor) ----------- */
__global__ __launch_bounds__(256) void kvproj(
        const float* __restrict__ A, const float* __restrict__ Wk,
        const float* __restrict__ Wv) {
    __shared__ float As[32][36];
    __shared__ float Ws[32][132];
    const float* W = blockIdx.x ? Wv : Wk;
    float* C = blockIdx.x ? g_v : g_k;
    int k0 = blockIdx.y * 128;
    int t = threadIdx.x;
    int mi = t >> 5, ni = t & 31;
    float acc[4][4];
#pragma unroll
    for (int i = 0; i < 4; i++)
#pragma unroll
        for (int j = 0; j < 4; j++) acc[i][j] = 0.f;

    for (int kb = 0; kb < 128; kb += 32) {
        int kg = k0 + kb;
#pragma unroll
        for (int p = 0; p < 4; p++) {
            int i = t + p * 256;
            As[i & 31][i >> 5] = A[(i >> 5) * FF + kg + (i & 31)];
        }
#pragma unroll
        for (int p = 0; p < 4; p++) {
            int i = t + p * 256;
            int kk = i >> 5, nq = i & 31;
            *(float4*)&Ws[kk][nq * 4] = *(const float4*)&W[(kg + kk) * DD + nq * 4];
        }
        __syncthreads();
#pragma unroll
        for (int kk = 0; kk < 32; kk++) {
            float4 a = *(float4*)&As[kk][mi * 4];
            float4 w = *(float4*)&Ws[kk][ni * 4];
            acc[0][0] += a.x*w.x; acc[0][1] += a.x*w.y; acc[0][2] += a.x*w.z; acc[0][3] += a.x*w.w;
            acc[1][0] += a.y*w.x; acc[1][1] += a.y*w.y; acc[1][2] += a.y*w.z; acc[1][3] += a.y*w.w;
            acc[2][0] += a.z*w.x; acc[2][1] += a.z*w.y; acc[2][2] += a.z*w.z; acc[2][3] += a.z*w.w;
            acc[3][0] += a.w*w.x; acc[3][1] += a.w*w.y; acc[3][2] += a.w*w.z; acc[3][3] += a.w*w.w;
        }
        __syncthreads();
    }
#pragma unroll
    for (int i = 0; i < 4; i++)
#pragma unroll
        for (int j = 0; j < 4; j++)
            atomicAdd(&C[(mi * 4 + i) * DD + ni * 4 + j], acc[i][j]);
}

/* ---------------- qprep: rope + scale + tf32 fragment pack (once per b) --- */
__global__ __launch_bounds__(256) void qprep_kernel(const int* __restrict__ ci) {
    int b = blockIdx.x, t = threadIdx.x;
    float pos = (float)ci[b];
    const float* qb = g_q + b * HH * DD;
    float4* qf4 = (float4*)(g_qf + b * HH * DD);
#pragma unroll
    for (int p = 0; p < 4; p++) {
        int fid = p * 256 + t;
        int kd = fid >> 6, mt = (fid >> 5) & 1, cc = (fid >> 3) & 3, gg = fid & 7;
        int r0 = mt * 16 + gg, r1 = r0 + 8;
        float4 hi;
        float e[4];
#pragma unroll
        for (int dj = 0; dj < 2; dj++) {
            int dcol = 8 * kd + cc + 4 * dj;
            float si, co;
            sincosf(pos * g_freq[dcol & 63], &si, &co);
#pragma unroll
            for (int rj = 0; rj < 2; rj++) {
                int r = rj ? r1 : r0;
                float a = qb[r * DD + dcol];
                float o = qb[r * DD + (dcol ^ 64)];
                float v = (dcol < 64) ? (a * co - o * si) : (a * co + o * si);
                e[dj * 2 + rj] = v * SCALE;
            }
        }
        hi.x = tff(e[0]); hi.y = tff(e[1]); hi.z = tff(e[2]); hi.w = tff(e[3]);
        int sfid = kd * 64 + mt * 32 + cc * 8 + ((gg + 2 * cc) & 7);
        qf4[sfid] = hi;
    }
}

/* ---------------- flash-decode attention v7 (q fragments via cp.async) ---- */
__global__ __launch_bounds__(256, 2) void attn_kernel(
        const float* __restrict__ Kc, const float* __restrict__ Vc,
        const int* __restrict__ ci) {
    extern __shared__ float sm[];
    float4* qfh4 = (float4*)sm;                 /* 1024 float4 */
    float*  psh  = sm + 4096;                   /* 2176 */
    float*  ppkf = sm + 6272;                   /* 2048 */
    float4* ppk4 = (float4*)ppkf;
    float*  kbuf = sm + 8320;                   /* 9216 */
    float*  vbuf = sm + 17536;                  /* 8704 */

    int b = blockIdx.x, sp = blockIdx.y;
    int idx = ci[b];
    int c0  = sp * CH;
    if (c0 > idx) return;

    int t = threadIdx.x, w = t >> 5, lane = t & 31;
    int g = lane >> 2, c = lane & 3;
    float pos = (float)idx;

    const float* Kb = Kc + (size_t)b * DD * LL;
    const float* Vb = Vc + (size_t)b * DD * LL;

    auto fillK = [&](int wi) {
        uint32_t dst = s2u(kbuf);
        const float* src = Kb + c0 + wi * WIN;
#pragma unroll
        for (int p = 0; p < 8; p++) {
            int i = t + p * 256; int d = i >> 4, u = i & 15;
            cpa16(dst + (uint32_t)(d * LDW + 4 * u) * 4, src + (size_t)d * LL + 4 * u);
        }
        cpcommit();
    };
    auto fillV = [&](int wi) {
        uint32_t dst = s2u(vbuf);
        const float* src = Vb + c0 + wi * WIN;
#pragma unroll
        for (int p = 0; p < 8; p++) {
            int i = t + p * 256; int d = i >> 4, u = i & 15;
            cpa16(dst + (uint32_t)(d * LDV + 4 * u) * 4, src + (size_t)d * LL + 4 * u);
        }
        cpcommit();
    };

    /* Q fragments (group 0), K0 (group 1), V0 (group 2) */
    {
        uint32_t dst = s2u(qfh4);
        const float* src = g_qf + b * HH * DD;
#pragma unroll
        for (int p = 0; p < 4; p++) {
            int i = t + p * 256;
            cpa16(dst + (uint32_t)i * 16, src + i * 4);
        }
        cpcommit();
    }
    fillK(0);
    fillV(0);

    int swz = c * 8 + ((g + 2 * c) & 7);

    float m_r[4] = {-1e30f, -1e30f, -1e30f, -1e30f};
    float s_r[4] = {0.f, 0.f, 0.f, 0.f};
    float acco[2][2][4];
#pragma unroll
    for (int mt = 0; mt < 2; mt++)
#pragma unroll
        for (int nt = 0; nt < 2; nt++)
#pragma unroll
            for (int r = 0; r < 4; r++) acco[mt][nt][r] = 0.f;

    for (int wi = 0; wi < 4; wi++) {
        int l0w = c0 + wi * WIN;
        int hot = (idx >= l0w) && (idx < l0w + WIN);
        int li = idx - l0w;

        cpwait1();              /* Q + K_wi ready (V_wi may be pending) */
        __syncthreads();
        if (hot) {
            if (t < 128) {
                float si, co;
                sincosf(pos * g_freq[t & 63], &si, &co);
                float a = g_k[b * DD + t];
                float o = g_k[b * DD + (t ^ 64)];
                float kr = (t < 64) ? (a * co - o * si) : (a * co + o * si);
                kbuf[t * LDW + li] += kr;
            }
            __syncthreads();
        }

        /* ---- QK ---- */
        float accq[2][4];
#pragma unroll
        for (int mt = 0; mt < 2; mt++)
#pragma unroll
            for (int r = 0; r < 4; r++) accq[mt][r] = 0.f;

#pragma unroll
        for (int kd = 0; kd < 16; kd++) {
            float4 ah0 = qfh4[kd * 64 +      swz];
            float4 ah1 = qfh4[kd * 64 + 32 + swz];
            float b0 = kbuf[(kd * 8 + c)     * LDW + w * 8 + g];
            float b1 = kbuf[(kd * 8 + c + 4) * LDW + w * 8 + g];
            uint32_t bb[2] = {f2tf(b0), f2tf(b1)};
            mma8(accq[0], (const uint32_t*)&ah0, bb);
            mma8(accq[1], (const uint32_t*)&ah1, bb);
        }
#pragma unroll
        for (int mt = 0; mt < 2; mt++) {
            int r0 = mt * 16 + g, cb = w * 8 + 2 * c;
            psh[r0 * LDP + cb]           = accq[mt][0];
            psh[r0 * LDP + cb + 1]       = accq[mt][1];
            psh[(r0 + 8) * LDP + cb]     = accq[mt][2];
            psh[(r0 + 8) * LDP + cb + 1] = accq[mt][3];
        }
        __syncthreads();
        if (wi < 3) fillK(wi + 1);

        /* ---- online softmax; probs fragment-packed ---- */
#pragma unroll
        for (int hj = 0; hj < 4; hj++) {
            int h = 4 * w + hj;
            float2 f = *(float2*)&psh[h * LDP + 2 * lane];
            if (l0w + WIN - 1 > idx) {
                int lb = l0w + 2 * lane;
                if (lb     > idx) f.x = -1e30f;
                if (lb + 1 > idx) f.y = -1e30f;
            }
            float tm = fmaxf(f.x, f.y);
            tm = fmaxf(tm, __shfl_xor_sync(0xffffffffu, tm, 16));
            tm = fmaxf(tm, __shfl_xor_sync(0xffffffffu, tm, 8));
            tm = fmaxf(tm, __shfl_xor_sync(0xffffffffu, tm, 4));
            tm = fmaxf(tm, __shfl_xor_sync(0xffffffffu, tm, 2));
            tm = fmaxf(tm, __shfl_xor_sync(0xffffffffu, tm, 1));
            float mn = fmaxf(m_r[hj], tm);
            float co = __expf(m_r[hj] - mn);
            float p0 = __expf(f.x - mn), p1 = __expf(f.y - mn);
            float ls = p0 + p1;
            ls += __shfl_xor_sync(0xffffffffu, ls, 16);
            ls += __shfl_xor_sync(0xffffffffu, ls, 8);
            ls += __shfl_xor_sync(0xffffffffu, ls, 4);
            ls += __shfl_xor_sync(0xffffffffu, ls, 2);
            ls += __shfl_xor_sync(0xffffffffu, ls, 1);
            s_r[hj] = s_r[hj] * co + ls;
            m_r[hj] = mn;

            int half = h >> 4, gp = h & 7, mt = (h >> 3) & 1;
            int kl = lane >> 2;
            int cpos0 = (2 * lane) & 7;
            int hi4 = cpos0 >> 2;
            int cp0 = cpos0 & 3, cp1 = cp0 + 1;
            int rowbase = (kl * 64 + half * 32 + ((gp + kl) & 7) * 4) * 4
                          + mt + 2 * hi4;
            int sk = (kl >> 1);
            ppkf[rowbase + ((cp0 + sk) & 3) * 4] = tff(p0);
            ppkf[rowbase + ((cp1 + sk) & 3) * 4] = tff(p1);
            if (lane == 0) psh[h * LDP + 64] = co;
        }

        if (wi == 3) cpwait0(); else cpwait1();
        __syncthreads();
        if (hot) {
            if (t < 128) vbuf[t * LDV + li] += g_v[b * DD + t];
            __syncthreads();
        }

        /* rescale PV accumulators */
        {
            float s0 = psh[(g)      * LDP + 64];
            float s1 = psh[(g + 8)  * LDP + 64];
            float s2 = psh[(g + 16) * LDP + 64];
            float s3 = psh[(g + 24) * LDP + 64];
#pragma unroll
            for (int nt = 0; nt < 2; nt++) {
                acco[0][nt][0] *= s0; acco[0][nt][1] *= s0;
                acco[0][nt][2] *= s1; acco[0][nt][3] *= s1;
                acco[1][nt][0] *= s2; acco[1][nt][1] *= s2;
                acco[1][nt][2] *= s3; acco[1][nt][3] *= s3;
            }
        }

        /* ---- PV: single-term tf32 V ---- */
#pragma unroll
        for (int kl = 0; kl < 8; kl++) {
            int pidx = kl * 64 + ((g + kl) & 7) * 4 + ((c + (kl >> 1)) & 3);
            float4 ap0f = ppk4[pidx];
            float4 ap1f = ppk4[pidx + 32];
#pragma unroll
            for (int nt = 0; nt < 2; nt++) {
                int d = w * 16 + nt * 8 + g;
                float v0 = vbuf[d * LDV + kl * 8 + c];
                float v1 = vbuf[d * LDV + kl * 8 + c + 4];
                uint32_t bh[2] = {f2tf(v0), f2tf(v1)};
                mma8(acco[0][nt], (const uint32_t*)&ap0f, bh);
                mma8(acco[1][nt], (const uint32_t*)&ap1f, bh);
            }
        }
        __syncthreads();
        if (wi < 3) fillV(wi + 1);
    }

    /* write partials */
    int pb = (b * NSPLIT + sp) * HH;
    if (lane == 0) {
#pragma unroll
        for (int hj = 0; hj < 4; hj++) {
            g_pm[pb + 4 * w + hj]   = m_r[hj];
            g_psum[pb + 4 * w + hj] = s_r[hj];
        }
    }
#pragma unroll
    for (int mt = 0; mt < 2; mt++)
#pragma unroll
        for (int nt = 0; nt < 2; nt++) {
            int h0 = mt * 16 + g;
            int dd = w * 16 + nt * 8 + 2 * c;
            g_po[(size_t)(pb + h0) * DD + dd]         = acco[mt][nt][0];
            g_po[(size_t)(pb + h0) * DD + dd + 1]     = acco[mt][nt][1];
            g_po[(size_t)(pb + h0 + 8) * DD + dd]     = acco[mt][nt][2];
            g_po[(size_t)(pb + h0 + 8) * DD + dd + 1] = acco[mt][nt][3];
        }
}

/* ---------------- combine (validity-aware) ------------------------------- */
__global__ void combine_kernel(const int* __restrict__ ci) {
    int bh = blockIdx.x;
    int b = bh >> 5, h = bh & 31;
    int d = threadIdx.x;
    int nv = (ci[b] >> 8) + 1;
    float m = -1e30f;
    for (int s = 0; s < nv; s++)
        m = fmaxf(m, g_pm[(b * NSPLIT + s) * HH + h]);
    float S = 0.f, acc = 0.f;
    for (int s = 0; s < nv; s++) {
        int ib = (b * NSPLIT + s) * HH + h;
        float w = __expf(g_pm[ib] - m);
        S   += w * g_psum[ib];
        acc += w * g_po[(size_t)ib * DD + d];
    }
    g_attn[(b * HH + h) * DD + d] = acc / S;
}

/* ---------------- launch ------------------------------------------------- */
extern "C" void kernel_launch(void* const* d_in, const int* in_sizes, int n_in,
                              void* d_out, int out_size) {
    const float* x  = (const float*)d_in[0];
    const float* Kc = (const float*)d_in[1];
    const float* Vc = (const float*)d_in[2];
    const float* Wq = (const float*)d_in[3];
    const float* Wk = (const float*)d_in[4];
    const float* Wv = (const float*)d_in[5];
    const float* Wo = (const float*)d_in[6];
    const int*   ci = (const int*)d_in[7];
    float* out = (float*)d_out;

    float *qp, *ap;
    cudaGetSymbolAddress((void**)&qp, g_q);
    cudaGetSymbolAddress((void**)&ap, g_attn);

    cudaFuncSetAttribute(tgemm32<true>,
                         cudaFuncAttributeMaxDynamicSharedMemorySize, 101376);
    cudaFuncSetAttribute(tgemm32<false>,
                         cudaFuncAttributeMaxDynamicSharedMemorySize, 101376);
    cudaFuncSetAttribute(attn_kernel,
                         cudaFuncAttributeMaxDynamicSharedMemorySize, 104960);

    zero_kernel<<<512, 256>>>(out);
    tgemm32<true><<<dim3(16, SPLITK), 256, 101376>>>(x, Wq, qp, 4096);
    kvproj<<<dim3(2, 32), 256>>>(x, Wk, Wv);
    qprep_kernel<<<32, 256>>>(ci);
    attn_kernel<<<dim3(32, NSPLIT), 256, 104960>>>(Kc, Vc, ci);
    combine_kernel<<<1024, 128>>>(ci);
    tgemm32<false><<<dim3(16, SPLITK), 256, 101376>>>(ap, Wo, out, 4096);
}

// round 14
// speedup vs baseline: 1.3516x; 1.0155x over previous
#include <cuda_runtime.h>
#include <math.h>
#include <stdint.h>

#define BB 32
#define FF 4096
#define HH 32
#define DD 128
#define LL 8192
#define NSPLIT 32
#define CH (LL/NSPLIT)          /* 256 */
#define WIN 64
#define LDW 72                  /* K window stride (floats) */
#define LDV 68                  /* V window stride (floats) */
#define LDP 68                  /* psh row stride (col 64 = corr) */
#define SCALE 0.08838834764831845f

/* ---------------- scratch ------------------------------------------------ */
__device__ float g_q[BB*HH*DD];
__device__ float g_qf[BB*HH*DD];    /* packed tf32 q fragments */
__device__ float g_k[BB*DD];
__device__ float g_kr[BB*DD];       /* roped k */
__device__ float g_v[BB*DD];
__device__ float g_attn[BB*HH*DD];
__device__ float g_pm[BB*NSPLIT*HH];
__device__ float g_psum[BB*NSPLIT*HH];
__device__ float g_po[BB*NSPLIT*HH*DD];
__device__ float g_freq[64];

/* ---------------- helpers ------------------------------------------------ */
__device__ __forceinline__ uint32_t s2u(const void* p) {
    return (uint32_t)__cvta_generic_to_shared(p);
}
__device__ __forceinline__ void cpa16(uint32_t s, const void* g) {
    asm volatile("cp.async.cg.shared.global [%0], [%1], 16;" :: "r"(s), "l"(g));
}
__device__ __forceinline__ void cpcommit() { asm volatile("cp.async.commit_group;"); }
__device__ __forceinline__ void cpwait0()  { asm volatile("cp.async.wait_group 0;"); }
__device__ __forceinline__ void cpwait1()  { asm volatile("cp.async.wait_group 1;"); }

__device__ __forceinline__ uint32_t f2tf(float x) {
    uint32_t r; asm("cvt.rna.tf32.f32 %0, %1;" : "=r"(r) : "f"(x)); return r;
}
__device__ __forceinline__ float tff(float x) { return __uint_as_float(f2tf(x)); }
__device__ __forceinline__ void mma8(float* d, const uint32_t* a, const uint32_t* b) {
    asm volatile("mma.sync.aligned.m16n8k8.row.col.f32.tf32.tf32.f32 "
        "{%0,%1,%2,%3},{%4,%5,%6,%7},{%8,%9},{%0,%1,%2,%3};"
        : "+f"(d[0]), "+f"(d[1]), "+f"(d[2]), "+f"(d[3])
        : "r"(a[0]), "r"(a[1]), "r"(a[2]), "r"(a[3]), "r"(b[0]), "r"(b[1]));
}

/* ---------------- zero + freq table -------------------------------------- */
__global__ void zero_kernel(float* __restrict__ out) {
    int i = blockIdx.x * 256 + threadIdx.x;
    g_q[i] = 0.f;
    out[i] = 0.f;
    if (i < BB*DD) { g_k[i] = 0.f; g_v[i] = 0.f; }
    if (i < 64) g_freq[i] = (float)exp(-(double)i * 0.14391156831212787);
}

/* ---------------- tensor GEMM v5: A 2-term (TWOA) or single x W single ----- */
#define SPLITK 16
#define KSL (FF/SPLITK)          /* 256 */
template<bool TWOA>
__global__ __launch_bounds__(256, 2) void tgemm32(
        const float* __restrict__ A, const float* __restrict__ W,
        float* __restrict__ C, int N) {
    extern __shared__ float sm[];
    float* As = sm;                  /* 8448 floats */
    float* Ws = sm + 8448;           /* 2 x 8448 floats */
    uint32_t ws_u = s2u(Ws);

    int n0 = blockIdx.x * 256;
    int k0 = blockIdx.y * KSL;
    int t = threadIdx.x, wp = t >> 5, lane = t & 31;
    int g = lane >> 2, c = lane & 3;

#pragma unroll
    for (int p = 0; p < 32; p++) {
        int i = t + p * 256;
        int m = i >> 8, k = i & 255;
        As[k * 33 + m] = A[m * FF + k0 + k];
    }
    auto loadW = [&](int kb, int buf) {
        const float* src = W + (size_t)(k0 + kb * 32) * N + n0;
#pragma unroll
        for (int p = 0; p < 8; p++) {
            int ci = t + p * 256;
            int kk = ci >> 6, u = ci & 63;
            cpa16(ws_u + (uint32_t)(buf * 8448 + kk * 264 + 4 * u) * 4,
                  src + (size_t)kk * N + 4 * u);
        }
        cpcommit();
    };
    loadW(0, 0);
    loadW(1, 1);

    float acc[2][4][4];
#pragma unroll
    for (int mt = 0; mt < 2; mt++)
#pragma unroll
        for (int nt = 0; nt < 4; nt++)
#pragma unroll
            for (int r = 0; r < 4; r++) acc[mt][nt][r] = 0.f;

    for (int kb = 0; kb < 8; kb++) {
        if (kb == 7) cpwait0(); else cpwait1();
        __syncthreads();
        const float* wsb = Ws + (kb & 1) * 8448;

#pragma unroll
        for (int ks = 0; ks < 4; ks++) {
            int kg = kb * 32 + ks * 8;
            uint32_t ahi[2][4], alo[2][4];
#pragma unroll
            for (int mt = 0; mt < 2; mt++) {
                float a0 = As[(kg + c)     * 33 + mt * 16 + g];
                float a1 = As[(kg + c)     * 33 + mt * 16 + g + 8];
                float a2 = As[(kg + c + 4) * 33 + mt * 16 + g];
                float a3 = As[(kg + c + 4) * 33 + mt * 16 + g + 8];
                ahi[mt][0] = f2tf(a0);
                ahi[mt][1] = f2tf(a1);
                ahi[mt][2] = f2tf(a2);
                ahi[mt][3] = f2tf(a3);
                if (TWOA) {
                    alo[mt][0] = f2tf(a0 - __uint_as_float(ahi[mt][0]));
                    alo[mt][1] = f2tf(a1 - __uint_as_float(ahi[mt][1]));
                    alo[mt][2] = f2tf(a2 - __uint_as_float(ahi[mt][2]));
                    alo[mt][3] = f2tf(a3 - __uint_as_float(ahi[mt][3]));
                }
            }
#pragma unroll
            for (int nt = 0; nt < 4; nt++) {
                float b0 = wsb[(ks * 8 + c)     * 264 + wp * 32 + nt * 8 + g];
                float b1 = wsb[(ks * 8 + c + 4) * 264 + wp * 32 + nt * 8 + g];
                uint32_t bhi[2] = {f2tf(b0), f2tf(b1)};
#pragma unroll
                for (int mt = 0; mt < 2; mt++) {
                    mma8(acc[mt][nt], ahi[mt], bhi);
                    if (TWOA) mma8(acc[mt][nt], alo[mt], bhi);
                }
            }
        }
        __syncthreads();
        if (kb < 6) loadW(kb + 2, kb & 1);
    }
#pragma unroll
    for (int mt = 0; mt < 2; mt++)
#pragma unroll
        for (int nt = 0; nt < 4; nt++) {
            int row = mt * 16 + g;
            int col = n0 + wp * 32 + nt * 8 + 2 * c;
            atomicAdd(&C[(row)     * N + col],     acc[mt][nt][0]);
            atomicAdd(&C[(row)     * N + col + 1], acc[mt][nt][1]);
            atomicAdd(&C[(row + 8) * N + col],     acc[mt][nt][2]);
            atomicAdd(&C[(row + 8) * N + col + 1], acc[mt][nt][3]);
        }
}

/* ---------------- k/v projection (fp32 FFMA — precision anchor) ----------- */
__global__ __launch_bounds__(256) void kvproj(
        const float* __restrict__ A, const float* __restrict__ Wk,
        const float* __restrict__ Wv) {
    __shared__ float As[32][36];
    __shared__ float Ws[32][132];
    const float* W = blockIdx.x ? Wv : Wk;
    float* C = blockIdx.x ? g_v : g_k;
    int k0 = blockIdx.y * 128;
    int t = threadIdx.x;
    int mi = t >> 5, ni = t & 31;
    float acc[4][4];
#pragma unroll
    for (int i = 0; i < 4; i++)
#pragma unroll
        for (int j = 0; j < 4; j++) acc[i][j] = 0.f;

    for (int kb = 0; kb < 128; kb += 32) {
        int kg = k0 + kb;
#pragma unroll
        for (int p = 0; p < 4; p++) {
            int i = t + p * 256;
            As[i & 31][i >> 5] = A[(i >> 5) * FF + kg + (i & 31)];
        }
#pragma unroll
        for (int p = 0; p < 4; p++) {
            int i = t + p * 256;
            int kk = i >> 5, nq = i & 31;
            *(float4*)&Ws[kk][nq * 4] = *(const float4*)&W[(kg + kk) * DD + nq * 4];
        }
        __syncthreads();
#pragma unroll
        for (int kk = 0; kk < 32; kk++) {
            float4 a = *(float4*)&As[kk][mi * 4];
            float4 w = *(float4*)&Ws[kk][ni * 4];
            acc[0][0] += a.x*w.x; acc[0][1] += a.x*w.y; acc[0][2] += a.x*w.z; acc[0][3] += a.x*w.w;
            acc[1][0] += a.y*w.x; acc[1][1] += a.y*w.y; acc[1][2] += a.y*w.z; acc[1][3] += a.y*w.w;
            acc[2][0] += a.z*w.x; acc[2][1] += a.z*w.y; acc[2][2] += a.z*w.z; acc[2][3] += a.z*w.w;
            acc[3][0] += a.w*w.x; acc[3][1] += a.w*w.y; acc[3][2] += a.w*w.z; acc[3][3] += a.w*w.w;
        }
        __syncthreads();
    }
#pragma unroll
    for (int i = 0; i < 4; i++)
#pragma unroll
        for (int j = 0; j < 4; j++)
            atomicAdd(&C[(mi * 4 + i) * DD + ni * 4 + j], acc[i][j]);
}

/* ---------------- qprep v2: grid (32,4); 1 fragment/thread + g_kr --------- */
__global__ __launch_bounds__(256) void qprep_kernel(const int* __restrict__ ci) {
    int b = blockIdx.x, seg = blockIdx.y, t = threadIdx.x;
    float pos = (float)ci[b];
    const float* qb = g_q + b * HH * DD;
    float4* qf4 = (float4*)(g_qf + b * HH * DD);

    int fid = seg * 256 + t;
    int kd = fid >> 6, mt = (fid >> 5) & 1, cc = (fid >> 3) & 3, gg = fid & 7;
    int r0 = mt * 16 + gg, r1 = r0 + 8;
    float4 hi;
    float e[4];
#pragma unroll
    for (int dj = 0; dj < 2; dj++) {
        int dcol = 8 * kd + cc + 4 * dj;
        float si, co;
        sincosf(pos * g_freq[dcol & 63], &si, &co);
#pragma unroll
        for (int rj = 0; rj < 2; rj++) {
            int r = rj ? r1 : r0;
            float a = qb[r * DD + dcol];
            float o = qb[r * DD + (dcol ^ 64)];
            float v = (dcol < 64) ? (a * co - o * si) : (a * co + o * si);
            e[dj * 2 + rj] = v * SCALE;
        }
    }
    hi.x = tff(e[0]); hi.y = tff(e[1]); hi.z = tff(e[2]); hi.w = tff(e[3]);
    int sfid = kd * 64 + mt * 32 + cc * 8 + ((gg + 2 * cc) & 7);
    qf4[sfid] = hi;

    /* roped k (seg 0, first 128 threads) */
    if (seg == 0 && t < 128) {
        float si, co;
        sincosf(pos * g_freq[t & 63], &si, &co);
        float a = g_k[b * DD + t];
        float o = g_k[b * DD + (t ^ 64)];
        g_kr[b * DD + t] = (t < 64) ? (a * co - o * si) : (a * co + o * si);
    }
}

/* ---------------- flash-decode attention v8 (g_kr; no hot sincosf) -------- */
__global__ __launch_bounds__(256, 2) void attn_kernel(
        const float* __restrict__ Kc, const float* __restrict__ Vc,
        const int* __restrict__ ci) {
    extern __shared__ float sm[];
    float4* qfh4 = (float4*)sm;                 /* 1024 float4 */
    float*  psh  = sm + 4096;                   /* 2176 */
    float*  ppkf = sm + 6272;                   /* 2048 */
    float4* ppk4 = (float4*)ppkf;
    float*  kbuf = sm + 8320;                   /* 9216 */
    float*  vbuf = sm + 17536;                  /* 8704 */

    int b = blockIdx.x, sp = blockIdx.y;
    int idx = ci[b];
    int c0  = sp * CH;
    if (c0 > idx) return;

    int t = threadIdx.x, w = t >> 5, lane = t & 31;
    int g = lane >> 2, c = lane & 3;

    const float* Kb = Kc + (size_t)b * DD * LL;
    const float* Vb = Vc + (size_t)b * DD * LL;

    auto fillK = [&](int wi) {
        uint32_t dst = s2u(kbuf);
        const float* src = Kb + c0 + wi * WIN;
#pragma unroll
        for (int p = 0; p < 8; p++) {
            int i = t + p * 256; int d = i >> 4, u = i & 15;
            cpa16(dst + (uint32_t)(d * LDW + 4 * u) * 4, src + (size_t)d * LL + 4 * u);
        }
        cpcommit();
    };
    auto fillV = [&](int wi) {
        uint32_t dst = s2u(vbuf);
        const float* src = Vb + c0 + wi * WIN;
#pragma unroll
        for (int p = 0; p < 8; p++) {
            int i = t + p * 256; int d = i >> 4, u = i & 15;
            cpa16(dst + (uint32_t)(d * LDV + 4 * u) * 4, src + (size_t)d * LL + 4 * u);
        }
        cpcommit();
    };

    /* Q fragments (group 0), K0 (group 1), V0 (group 2) */
    {
        uint32_t dst = s2u(qfh4);
        const float* src = g_qf + b * HH * DD;
#pragma unroll
        for (int p = 0; p < 4; p++) {
            int i = t + p * 256;
            cpa16(dst + (uint32_t)i * 16, src + i * 4);
        }
        cpcommit();
    }
    fillK(0);
    fillV(0);

    int swz = c * 8 + ((g + 2 * c) & 7);

    float m_r[4] = {-1e30f, -1e30f, -1e30f, -1e30f};
    float s_r[4] = {0.f, 0.f, 0.f, 0.f};
    float acco[2][2][4];
#pragma unroll
    for (int mt = 0; mt < 2; mt++)
#pragma unroll
        for (int nt = 0; nt < 2; nt++)
#pragma unroll
            for (int r = 0; r < 4; r++) acco[mt][nt][r] = 0.f;

    for (int wi = 0; wi < 4; wi++) {
        int l0w = c0 + wi * WIN;
        int hot = (idx >= l0w) && (idx < l0w + WIN);
        int li = idx - l0w;

        cpwait1();              /* Q + K_wi ready (V_wi may be pending) */
        __syncthreads();
        if (hot) {
            if (t < 128) kbuf[t * LDW + li] += g_kr[b * DD + t];
            __syncthreads();
        }

        /* ---- QK ---- */
        float accq[2][4];
#pragma unroll
        for (int mt = 0; mt < 2; mt++)
#pragma unroll
            for (int r = 0; r < 4; r++) accq[mt][r] = 0.f;

#pragma unroll
        for (int kd = 0; kd < 16; kd++) {
            float4 ah0 = qfh4[kd * 64 +      swz];
            float4 ah1 = qfh4[kd * 64 + 32 + swz];
            float b0 = kbuf[(kd * 8 + c)     * LDW + w * 8 + g];
            float b1 = kbuf[(kd * 8 + c + 4) * LDW + w * 8 + g];
            uint32_t bb[2] = {f2tf(b0), f2tf(b1)};
            mma8(accq[0], (const uint32_t*)&ah0, bb);
            mma8(accq[1], (const uint32_t*)&ah1, bb);
        }
#pragma unroll
        for (int mt = 0; mt < 2; mt++) {
            int r0 = mt * 16 + g, cb = w * 8 + 2 * c;
            psh[r0 * LDP + cb]           = accq[mt][0];
            psh[r0 * LDP + cb + 1]       = accq[mt][1];
            psh[(r0 + 8) * LDP + cb]     = accq[mt][2];
            psh[(r0 + 8) * LDP + cb + 1] = accq[mt][3];
        }
        __syncthreads();
        if (wi < 3) fillK(wi + 1);

        /* ---- online softmax; probs fragment-packed ---- */
#pragma unroll
        for (int hj = 0; hj < 4; hj++) {
            int h = 4 * w + hj;
            float2 f = *(float2*)&psh[h * LDP + 2 * lane];
            if (l0w + WIN - 1 > idx) {
                int lb = l0w + 2 * lane;
                if (lb     > idx) f.x = -1e30f;
                if (lb + 1 > idx) f.y = -1e30f;
            }
            float tm = fmaxf(f.x, f.y);
            tm = fmaxf(tm, __shfl_xor_sync(0xffffffffu, tm, 16));
            tm = fmaxf(tm, __shfl_xor_sync(0xffffffffu, tm, 8));
            tm = fmaxf(tm, __shfl_xor_sync(0xffffffffu, tm, 4));
            tm = fmaxf(tm, __shfl_xor_sync(0xffffffffu, tm, 2));
            tm = fmaxf(tm, __shfl_xor_sync(0xffffffffu, tm, 1));
            float mn = fmaxf(m_r[hj], tm);
            float co = __expf(m_r[hj] - mn);
            float p0 = __expf(f.x - mn), p1 = __expf(f.y - mn);
            float ls = p0 + p1;
            ls += __shfl_xor_sync(0xffffffffu, ls, 16);
            ls += __shfl_xor_sync(0xffffffffu, ls, 8);
            ls += __shfl_xor_sync(0xffffffffu, ls, 4);
            ls += __shfl_xor_sync(0xffffffffu, ls, 2);
            ls += __shfl_xor_sync(0xffffffffu, ls, 1);
            s_r[hj] = s_r[hj] * co + ls;
            m_r[hj] = mn;

            int half = h >> 4, gp = h & 7, mt = (h >> 3) & 1;
            int kl = lane >> 2;
            int cpos0 = (2 * lane) & 7;
            int hi4 = cpos0 >> 2;
            int cp0 = cpos0 & 3, cp1 = cp0 + 1;
            int rowbase = (kl * 64 + half * 32 + ((gp + kl) & 7) * 4) * 4
                          + mt + 2 * hi4;
            int sk = (kl >> 1);
            ppkf[rowbase + ((cp0 + sk) & 3) * 4] = tff(p0);
            ppkf[rowbase + ((cp1 + sk) & 3) * 4] = tff(p1);
            if (lane == 0) psh[h * LDP + 64] = co;
        }

        if (wi == 3) cpwait0(); else cpwait1();
        __syncthreads();
        if (hot) {
            if (t < 128) vbuf[t * LDV + li] += g_v[b * DD + t];
            __syncthreads();
        }

        /* rescale PV accumulators */
        {
            float s0 = psh[(g)      * LDP + 64];
            float s1 = psh[(g + 8)  * LDP + 64];
            float s2 = psh[(g + 16) * LDP + 64];
            float s3 = psh[(g + 24) * LDP + 64];
#pragma unroll
            for (int nt = 0; nt < 2; nt++) {
                acco[0][nt][0] *= s0; acco[0][nt][1] *= s0;
                acco[0][nt][2] *= s1; acco[0][nt][3] *= s1;
                acco[1][nt][0] *= s2; acco[1][nt][1] *= s2;
                acco[1][nt][2] *= s3; acco[1][nt][3] *= s3;
            }
        }

        /* ---- PV: single-term tf32 V ---- */
#pragma unroll
        for (int kl = 0; kl < 8; kl++) {
            int pidx = kl * 64 + ((g + kl) & 7) * 4 + ((c + (kl >> 1)) & 3);
            float4 ap0f = ppk4[pidx];
            float4 ap1f = ppk4[pidx + 32];
#pragma unroll
            for (int nt = 0; nt < 2; nt++) {
                int d = w * 16 + nt * 8 + g;
                float v0 = vbuf[d * LDV + kl * 8 + c];
                float v1 = vbuf[d * LDV + kl * 8 + c + 4];
                uint32_t bh[2] = {f2tf(v0), f2tf(v1)};
                mma8(acco[0][nt], (const uint32_t*)&ap0f, bh);
                mma8(acco[1][nt], (const uint32_t*)&ap1f, bh);
            }
        }
        __syncthreads();
        if (wi < 3) fillV(wi + 1);
    }

    /* write partials */
    int pb = (b * NSPLIT + sp) * HH;
    if (lane == 0) {
#pragma unroll
        for (int hj = 0; hj < 4; hj++) {
            g_pm[pb + 4 * w + hj]   = m_r[hj];
            g_psum[pb + 4 * w + hj] = s_r[hj];
        }
    }
#pragma unroll
    for (int mt = 0; mt < 2; mt++)
#pragma unroll
        for (int nt = 0; nt < 2; nt++) {
            int h0 = mt * 16 + g;
            int dd = w * 16 + nt * 8 + 2 * c;
            g_po[(size_t)(pb + h0) * DD + dd]         = acco[mt][nt][0];
            g_po[(size_t)(pb + h0) * DD + dd + 1]     = acco[mt][nt][1];
            g_po[(size_t)(pb + h0 + 8) * DD + dd]     = acco[mt][nt][2];
            g_po[(size_t)(pb + h0 + 8) * DD + dd + 1] = acco[mt][nt][3];
        }
}

/* ---------------- combine (validity-aware) ------------------------------- */
__global__ void combine_kernel(const int* __restrict__ ci) {
    int bh = blockIdx.x;
    int b = bh >> 5, h = bh & 31;
    int d = threadIdx.x;
    int nv = (ci[b] >> 8) + 1;
    float m = -1e30f;
    for (int s = 0; s < nv; s++)
        m = fmaxf(m, g_pm[(b * NSPLIT + s) * HH + h]);
    float S = 0.f, acc = 0.f;
    for (int s = 0; s < nv; s++) {
        int ib = (b * NSPLIT + s) * HH + h;
        float w = __expf(g_pm[ib] - m);
        S   += w * g_psum[ib];
        acc += w * g_po[(size_t)ib * DD + d];
    }
    g_attn[(b * HH + h) * DD + d] = acc / S;
}

/* ---------------- launch ------------------------------------------------- */
extern "C" void kernel_launch(void* const* d_in, const int* in_sizes, int n_in,
                              void* d_out, int out_size) {
    const float* x  = (const float*)d_in[0];
    const float* Kc = (const float*)d_in[1];
    const float* Vc = (const float*)d_in[2];
    const float* Wq = (const float*)d_in[3];
    const float* Wk = (const float*)d_in[4];
    const float* Wv = (const float*)d_in[5];
    const float* Wo = (const float*)d_in[6];
    const int*   ci = (const int*)d_in[7];
    float* out = (float*)d_out;

    float *qp, *ap;
    cudaGetSymbolAddress((void**)&qp, g_q);
    cudaGetSymbolAddress((void**)&ap, g_attn);

    cudaFuncSetAttribute(tgemm32<true>,
                         cudaFuncAttributeMaxDynamicSharedMemorySize, 101376);
    cudaFuncSetAttribute(tgemm32<false>,
                         cudaFuncAttributeMaxDynamicSharedMemorySize, 101376);
    cudaFuncSetAttribute(attn_kernel,
                         cudaFuncAttributeMaxDynamicSharedMemorySize, 104960);

    zero_kernel<<<512, 256>>>(out);
    tgemm32<true><<<dim3(16, SPLITK), 256, 101376>>>(x, Wq, qp, 4096);
    kvproj<<<dim3(2, 32), 256>>>(x, Wk, Wv);
    qprep_kernel<<<dim3(32, 4), 256>>>(ci);
    attn_kernel<<<dim3(32, NSPLIT), 256, 104960>>>(Kc, Vc, ci);
    combine_kernel<<<1024, 128>>>(ci);
    tgemm32<false><<<dim3(16, SPLITK), 256, 101376>>>(ap, Wo, out, 4096);
}

// round 15
// speedup vs baseline: 1.4059x; 1.0402x over previous
#include <cuda_runtime.h>
#include <math.h>
#include <stdint.h>

#define BB 32
#define FF 4096
#define HH 32
#define DD 128
#define LL 8192
#define NSPLIT 32
#define CH (LL/NSPLIT)          /* 256 */
#define WIN 64
#define LDW 72                  /* K window stride (floats) */
#define LDV 68                  /* V window stride (floats) */
#define LDP 68                  /* psh row stride (col 64 = corr) */
#define SCALE 0.08838834764831845f

/* ---------------- scratch ------------------------------------------------ */
__device__ float g_q[BB*HH*DD];
__device__ float g_qf[BB*HH*DD];    /* packed tf32 q fragments */
__device__ float g_k[BB*DD];
__device__ float g_kr[BB*DD];       /* roped k */
__device__ float g_v[BB*DD];
__device__ float g_attn[BB*HH*DD];
__device__ float g_pm[BB*NSPLIT*HH];
__device__ float g_psum[BB*NSPLIT*HH];
__device__ float g_po[BB*NSPLIT*HH*DD];
__device__ float g_freq[64];

/* ---------------- helpers ------------------------------------------------ */
__device__ __forceinline__ uint32_t s2u(const void* p) {
    return (uint32_t)__cvta_generic_to_shared(p);
}
__device__ __forceinline__ void cpa16(uint32_t s, const void* g) {
    asm volatile("cp.async.cg.shared.global [%0], [%1], 16;" :: "r"(s), "l"(g));
}
__device__ __forceinline__ void cpcommit() { asm volatile("cp.async.commit_group;"); }
__device__ __forceinline__ void cpwait0()  { asm volatile("cp.async.wait_group 0;"); }
__device__ __forceinline__ void cpwait1()  { asm volatile("cp.async.wait_group 1;"); }

__device__ __forceinline__ uint32_t f2tf(float x) {
    uint32_t r; asm("cvt.rna.tf32.f32 %0, %1;" : "=r"(r) : "f"(x)); return r;
}
__device__ __forceinline__ float tff(float x) { return __uint_as_float(f2tf(x)); }
__device__ __forceinline__ void mma8(float* d, const uint32_t* a, const uint32_t* b) {
    asm volatile("mma.sync.aligned.m16n8k8.row.col.f32.tf32.tf32.f32 "
        "{%0,%1,%2,%3},{%4,%5,%6,%7},{%8,%9},{%0,%1,%2,%3};"
        : "+f"(d[0]), "+f"(d[1]), "+f"(d[2]), "+f"(d[3])
        : "r"(a[0]), "r"(a[1]), "r"(a[2]), "r"(a[3]), "r"(b[0]), "r"(b[1]));
}

/* ---------------- zero + freq table (out zeroing moved to combine) ------- */
__global__ void zero_kernel() {
    int i = blockIdx.x * 256 + threadIdx.x;
    g_q[i] = 0.f;
    if (i < BB*DD) { g_k[i] = 0.f; g_v[i] = 0.f; }
    if (i < 64) g_freq[i] = (float)exp(-(double)i * 0.14391156831212787);
}

/* ---------------- tensor GEMM v6 ------------------------------------------
 * TWOA=true : q-proj, As[k][m] scalar layout, 2-term A x single W (unchanged)
 * TWOA=false: o-proj, As holds PRE-CONVERTED tf32 A in fragment order ->
 *             inner A-loads are 2 x LDS.128 per ks.                        */
#define SPLITK 16
#define KSL (FF/SPLITK)          /* 256 */
template<bool TWOA>
__global__ __launch_bounds__(256, 2) void tgemm32(
        const float* __restrict__ A, const float* __restrict__ W,
        float* __restrict__ C, int N) {
    extern __shared__ float sm[];
    float* As = sm;                  /* 8448 floats (frag mode uses 8192) */
    float* Ws = sm + 8448;           /* 2 x 8448 floats */
    const float4* As4 = (const float4*)As;
    uint32_t ws_u = s2u(Ws);

    int n0 = blockIdx.x * 256;
    int k0 = blockIdx.y * KSL;
    int t = threadIdx.x, wp = t >> 5, lane = t & 31;
    int g = lane >> 2, c = lane & 3;

    if (TWOA) {
#pragma unroll
        for (int p = 0; p < 32; p++) {
            int i = t + p * 256;
            int m = i >> 8, k = i & 255;
            As[k * 33 + m] = A[m * FF + k0 + k];
        }
    } else {
        /* pre-convert to tf32, store in MMA fragment order */
#pragma unroll
        for (int p = 0; p < 32; p++) {
            int i = t + p * 256;
            int m = i >> 8, k = i & 255;
            float val = tff(A[m * FF + k0 + k]);
            int kslot = k >> 3, c2 = k & 3, hi4 = (k >> 2) & 1;
            int mt = m >> 4, g2 = m & 7, m8 = (m >> 3) & 1;
            int fidx = (kslot * 2 + mt) * 32 + c2 * 8 + ((g2 + 2 * c2) & 7);
            As[fidx * 4 + hi4 * 2 + m8] = val;
        }
    }
    auto loadW = [&](int kb, int buf) {
        const float* src = W + (size_t)(k0 + kb * 32) * N + n0;
#pragma unroll
        for (int p = 0; p < 8; p++) {
            int ci = t + p * 256;
            int kk = ci >> 6, u = ci & 63;
            cpa16(ws_u + (uint32_t)(buf * 8448 + kk * 264 + 4 * u) * 4,
                  src + (size_t)kk * N + 4 * u);
        }
        cpcommit();
    };
    loadW(0, 0);
    loadW(1, 1);

    int swz = c * 8 + ((g + 2 * c) & 7);

    float acc[2][4][4];
#pragma unroll
    for (int mt = 0; mt < 2; mt++)
#pragma unroll
        for (int nt = 0; nt < 4; nt++)
#pragma unroll
            for (int r = 0; r < 4; r++) acc[mt][nt][r] = 0.f;

    for (int kb = 0; kb < 8; kb++) {
        if (kb == 7) cpwait0(); else cpwait1();
        __syncthreads();
        const float* wsb = Ws + (kb & 1) * 8448;

#pragma unroll
        for (int ks = 0; ks < 4; ks++) {
            int kg = kb * 32 + ks * 8;
            uint32_t ahi[2][4], alo[2][4];
            if (TWOA) {
#pragma unroll
                for (int mt = 0; mt < 2; mt++) {
                    float a0 = As[(kg + c)     * 33 + mt * 16 + g];
                    float a1 = As[(kg + c)     * 33 + mt * 16 + g + 8];
                    float a2 = As[(kg + c + 4) * 33 + mt * 16 + g];
                    float a3 = As[(kg + c + 4) * 33 + mt * 16 + g + 8];
                    ahi[mt][0] = f2tf(a0);
                    ahi[mt][1] = f2tf(a1);
                    ahi[mt][2] = f2tf(a2);
                    ahi[mt][3] = f2tf(a3);
                    alo[mt][0] = f2tf(a0 - __uint_as_float(ahi[mt][0]));
                    alo[mt][1] = f2tf(a1 - __uint_as_float(ahi[mt][1]));
                    alo[mt][2] = f2tf(a2 - __uint_as_float(ahi[mt][2]));
                    alo[mt][3] = f2tf(a3 - __uint_as_float(ahi[mt][3]));
                }
            } else {
                int kslot = kb * 4 + ks;
                float4 af0 = As4[(kslot * 2 + 0) * 32 + swz];
                float4 af1 = As4[(kslot * 2 + 1) * 32 + swz];
                ahi[0][0] = __float_as_uint(af0.x); ahi[0][1] = __float_as_uint(af0.y);
                ahi[0][2] = __float_as_uint(af0.z); ahi[0][3] = __float_as_uint(af0.w);
                ahi[1][0] = __float_as_uint(af1.x); ahi[1][1] = __float_as_uint(af1.y);
                ahi[1][2] = __float_as_uint(af1.z); ahi[1][3] = __float_as_uint(af1.w);
            }
#pragma unroll
            for (int nt = 0; nt < 4; nt++) {
                float b0 = wsb[(ks * 8 + c)     * 264 + wp * 32 + nt * 8 + g];
                float b1 = wsb[(ks * 8 + c + 4) * 264 + wp * 32 + nt * 8 + g];
                uint32_t bhi[2] = {f2tf(b0), f2tf(b1)};
#pragma unroll
                for (int mt = 0; mt < 2; mt++) {
                    mma8(acc[mt][nt], ahi[mt], bhi);
                    if (TWOA) mma8(acc[mt][nt], alo[mt], bhi);
                }
            }
        }
        __syncthreads();
        if (kb < 6) loadW(kb + 2, kb & 1);
    }
#pragma unroll
    for (int mt = 0; mt < 2; mt++)
#pragma unroll
        for (int nt = 0; nt < 4; nt++) {
            int row = mt * 16 + g;
            int col = n0 + wp * 32 + nt * 8 + 2 * c;
            atomicAdd(&C[(row)     * N + col],     acc[mt][nt][0]);
            atomicAdd(&C[(row)     * N + col + 1], acc[mt][nt][1]);
            atomicAdd(&C[(row + 8) * N + col],     acc[mt][nt][2]);
            atomicAdd(&C[(row + 8) * N + col + 1], acc[mt][nt][3]);
        }
}

/* ---------------- k/v projection (fp32 FFMA — precision anchor) ----------- */
__global__ __launch_bounds__(256) void kvproj(
        const float* __restrict__ A, const float* __restrict__ Wk,
        const float* __restrict__ Wv) {
    __shared__ float As[32][36];
    __shared__ float Ws[32][132];
    const float* W = blockIdx.x ? Wv : Wk;
    float* C = blockIdx.x ? g_v : g_k;
    int k0 = blockIdx.y * 128;
    int t = threadIdx.x;
    int mi = t >> 5, ni = t & 31;
    float acc[4][4];
#pragma unroll
    for (int i = 0; i < 4; i++)
#pragma unroll
        for (int j = 0; j < 4; j++) acc[i][j] = 0.f;

    for (int kb = 0; kb < 128; kb += 32) {
        int kg = k0 + kb;
#pragma unroll
        for (int p = 0; p < 4; p++) {
            int i = t + p * 256;
            As[i & 31][i >> 5] = A[(i >> 5) * FF + kg + (i & 31)];
        }
#pragma unroll
        for (int p = 0; p < 4; p++) {
            int i = t + p * 256;
            int kk = i >> 5, nq = i & 31;
            *(float4*)&Ws[kk][nq * 4] = *(const float4*)&W[(kg + kk) * DD + nq * 4];
        }
        __syncthreads();
#pragma unroll
        for (int kk = 0; kk < 32; kk++) {
            float4 a = *(float4*)&As[kk][mi * 4];
            float4 w = *(float4*)&Ws[kk][ni * 4];
            acc[0][0] += a.x*w.x; acc[0][1] += a.x*w.y; acc[0][2] += a.x*w.z; acc[0][3] += a.x*w.w;
            acc[1][0] += a.y*w.x; acc[1][1] += a.y*w.y; acc[1][2] += a.y*w.z; acc[1][3] += a.y*w.w;
            acc[2][0] += a.z*w.x; acc[2][1] += a.z*w.y; acc[2][2] += a.z*w.z; acc[2][3] += a.z*w.w;
            acc[3][0] += a.w*w.x; acc[3][1] += a.w*w.y; acc[3][2] += a.w*w.z; acc[3][3] += a.w*w.w;
        }
        __syncthreads();
    }
#pragma unroll
    for (int i = 0; i < 4; i++)
#pragma unroll
        for (int j = 0; j < 4; j++)
            atomicAdd(&C[(mi * 4 + i) * DD + ni * 4 + j], acc[i][j]);
}

/* ---------------- qprep v3: MLP-batched loads, grid (32,4) ---------------- */
__global__ __launch_bounds__(256) void qprep_kernel(const int* __restrict__ ci) {
    int b = blockIdx.x, seg = blockIdx.y, t = threadIdx.x;
    float pos = (float)ci[b];
    const float* qb = g_q + b * HH * DD;
    float4* qf4 = (float4*)(g_qf + b * HH * DD);

    int fid = seg * 256 + t;
    int kd = fid >> 6, mt = (fid >> 5) & 1, cc = (fid >> 3) & 3, gg = fid & 7;
    int r0 = mt * 16 + gg, r1 = r0 + 8;
    int d0 = 8 * kd + cc, d1 = d0 + 4;

    /* batch all 8 loads (MLP) before the trig chain */
    float a00 = qb[r0 * DD + d0];
    float a01 = qb[r1 * DD + d0];
    float o00 = qb[r0 * DD + (d0 ^ 64)];
    float o01 = qb[r1 * DD + (d0 ^ 64)];
    float a10 = qb[r0 * DD + d1];
    float a11 = qb[r1 * DD + d1];
    float o10 = qb[r0 * DD + (d1 ^ 64)];
    float o11 = qb[r1 * DD + (d1 ^ 64)];
    float f0 = g_freq[d0 & 63], f1 = g_freq[d1 & 63];

    float s0, c0, s1, c1;
    sincosf(pos * f0, &s0, &c0);
    sincosf(pos * f1, &s1, &c1);

    float sgn0 = (d0 < 64) ? -1.f : 1.f;
    float sgn1 = (d1 < 64) ? -1.f : 1.f;
    float4 hi;
    hi.x = tff((a00 * c0 + sgn0 * o00 * s0) * SCALE);
    hi.y = tff((a01 * c0 + sgn0 * o01 * s0) * SCALE);
    hi.z = tff((a10 * c1 + sgn1 * o10 * s1) * SCALE);
    hi.w = tff((a11 * c1 + sgn1 * o11 * s1) * SCALE);
    int sfid = kd * 64 + mt * 32 + cc * 8 + ((gg + 2 * cc) & 7);
    qf4[sfid] = hi;

    if (seg == 0 && t < 128) {
        float a = g_k[b * DD + t];
        float o = g_k[b * DD + (t ^ 64)];
        float si, co;
        sincosf(pos * g_freq[t & 63], &si, &co);
        g_kr[b * DD + t] = (t < 64) ? (a * co - o * si) : (a * co + o * si);
    }
}

/* ---------------- flash-decode attention v8 (unchanged from R14) ---------- */
__global__ __launch_bounds__(256, 2) void attn_kernel(
        const float* __restrict__ Kc, const float* __restrict__ Vc,
        const int* __restrict__ ci) {
    extern __shared__ float sm[];
    float4* qfh4 = (float4*)sm;
    float*  psh  = sm + 4096;
    float*  ppkf = sm + 6272;
    float4* ppk4 = (float4*)ppkf;
    float*  kbuf = sm + 8320;
    float*  vbuf = sm + 17536;

    int b = blockIdx.x, sp = blockIdx.y;
    int idx = ci[b];
    int c0  = sp * CH;
    if (c0 > idx) return;

    int t = threadIdx.x, w = t >> 5, lane = t & 31;
    int g = lane >> 2, c = lane & 3;

    const float* Kb = Kc + (size_t)b * DD * LL;
    const float* Vb = Vc + (size_t)b * DD * LL;

    auto fillK = [&](int wi) {
        uint32_t dst = s2u(kbuf);
        const float* src = Kb + c0 + wi * WIN;
#pragma unroll
        for (int p = 0; p < 8; p++) {
            int i = t + p * 256; int d = i >> 4, u = i & 15;
            cpa16(dst + (uint32_t)(d * LDW + 4 * u) * 4, src + (size_t)d * LL + 4 * u);
        }
        cpcommit();
    };
    auto fillV = [&](int wi) {
        uint32_t dst = s2u(vbuf);
        const float* src = Vb + c0 + wi * WIN;
#pragma unroll
        for (int p = 0; p < 8; p++) {
            int i = t + p * 256; int d = i >> 4, u = i & 15;
            cpa16(dst + (uint32_t)(d * LDV + 4 * u) * 4, src + (size_t)d * LL + 4 * u);
        }
        cpcommit();
    };

    {
        uint32_t dst = s2u(qfh4);
        const float* src = g_qf + b * HH * DD;
#pragma unroll
        for (int p = 0; p < 4; p++) {
            int i = t + p * 256;
            cpa16(dst + (uint32_t)i * 16, src + i * 4);
        }
        cpcommit();
    }
    fillK(0);
    fillV(0);

    int swz = c * 8 + ((g + 2 * c) & 7);

    float m_r[4] = {-1e30f, -1e30f, -1e30f, -1e30f};
    float s_r[4] = {0.f, 0.f, 0.f, 0.f};
    float acco[2][2][4];
#pragma unroll
    for (int mt = 0; mt < 2; mt++)
#pragma unroll
        for (int nt = 0; nt < 2; nt++)
#pragma unroll
            for (int r = 0; r < 4; r++) acco[mt][nt][r] = 0.f;

    for (int wi = 0; wi < 4; wi++) {
        int l0w = c0 + wi * WIN;
        int hot = (idx >= l0w) && (idx < l0w + WIN);
        int li = idx - l0w;

        cpwait1();
        __syncthreads();
        if (hot) {
            if (t < 128) kbuf[t * LDW + li] += g_kr[b * DD + t];
            __syncthreads();
        }

        float accq[2][4];
#pragma unroll
        for (int mt = 0; mt < 2; mt++)
#pragma unroll
            for (int r = 0; r < 4; r++) accq[mt][r] = 0.f;

#pragma unroll
        for (int kd = 0; kd < 16; kd++) {
            float4 ah0 = qfh4[kd * 64 +      swz];
            float4 ah1 = qfh4[kd * 64 + 32 + swz];
            float b0 = kbuf[(kd * 8 + c)     * LDW + w * 8 + g];
            float b1 = kbuf[(kd * 8 + c + 4) * LDW + w * 8 + g];
            uint32_t bb[2] = {f2tf(b0), f2tf(b1)};
            mma8(accq[0], (const uint32_t*)&ah0, bb);
            mma8(accq[1], (const uint32_t*)&ah1, bb);
        }
#pragma unroll
        for (int mt = 0; mt < 2; mt++) {
            int r0 = mt * 16 + g, cb = w * 8 + 2 * c;
            psh[r0 * LDP + cb]           = accq[mt][0];
            psh[r0 * LDP + cb + 1]       = accq[mt][1];
            psh[(r0 + 8) * LDP + cb]     = accq[mt][2];
            psh[(r0 + 8) * LDP + cb + 1] = accq[mt][3];
        }
        __syncthreads();
        if (wi < 3) fillK(wi + 1);

#pragma unroll
        for (int hj = 0; hj < 4; hj++) {
            int h = 4 * w + hj;
            float2 f = *(float2*)&psh[h * LDP + 2 * lane];
            if (l0w + WIN - 1 > idx) {
                int lb = l0w + 2 * lane;
                if (lb     > idx) f.x = -1e30f;
                if (lb + 1 > idx) f.y = -1e30f;
            }
            float tm = fmaxf(f.x, f.y);
            tm = fmaxf(tm, __shfl_xor_sync(0xffffffffu, tm, 16));
            tm = fmaxf(tm, __shfl_xor_sync(0xffffffffu, tm, 8));
            tm = fmaxf(tm, __shfl_xor_sync(0xffffffffu, tm, 4));
            tm = fmaxf(tm, __shfl_xor_sync(0xffffffffu, tm, 2));
            tm = fmaxf(tm, __shfl_xor_sync(0xffffffffu, tm, 1));
            float mn = fmaxf(m_r[hj], tm);
            float co = __expf(m_r[hj] - mn);
            float p0 = __expf(f.x - mn), p1 = __expf(f.y - mn);
            float ls = p0 + p1;
            ls += __shfl_xor_sync(0xffffffffu, ls, 16);
            ls += __shfl_xor_sync(0xffffffffu, ls, 8);
            ls += __shfl_xor_sync(0xffffffffu, ls, 4);
            ls += __shfl_xor_sync(0xffffffffu, ls, 2);
            ls += __shfl_xor_sync(0xffffffffu, ls, 1);
            s_r[hj] = s_r[hj] * co + ls;
            m_r[hj] = mn;

            int half = h >> 4, gp = h & 7, mt = (h >> 3) & 1;
            int kl = lane >> 2;
            int cpos0 = (2 * lane) & 7;
            int hi4 = cpos0 >> 2;
            int cp0 = cpos0 & 3, cp1 = cp0 + 1;
            int rowbase = (kl * 64 + half * 32 + ((gp + kl) & 7) * 4) * 4
                          + mt + 2 * hi4;
            int sk = (kl >> 1);
            ppkf[rowbase + ((cp0 + sk) & 3) * 4] = tff(p0);
            ppkf[rowbase + ((cp1 + sk) & 3) * 4] = tff(p1);
            if (lane == 0) psh[h * LDP + 64] = co;
        }

        if (wi == 3) cpwait0(); else cpwait1();
        __syncthreads();
        if (hot) {
            if (t < 128) vbuf[t * LDV + li] += g_v[b * DD + t];
            __syncthreads();
        }

        {
            float s0 = psh[(g)      * LDP + 64];
            float s1 = psh[(g + 8)  * LDP + 64];
            float s2 = psh[(g + 16) * LDP + 64];
            float s3 = psh[(g + 24) * LDP + 64];
#pragma unroll
            for (int nt = 0; nt < 2; nt++) {
                acco[0][nt][0] *= s0; acco[0][nt][1] *= s0;
                acco[0][nt][2] *= s1; acco[0][nt][3] *= s1;
                acco[1][nt][0] *= s2; acco[1][nt][1] *= s2;
                acco[1][nt][2] *= s3; acco[1][nt][3] *= s3;
            }
        }

#pragma unroll
        for (int kl = 0; kl < 8; kl++) {
            int pidx = kl * 64 + ((g + kl) & 7) * 4 + ((c + (kl >> 1)) & 3);
            float4 ap0f = ppk4[pidx];
            float4 ap1f = ppk4[pidx + 32];
#pragma unroll
            for (int nt = 0; nt < 2; nt++) {
                int d = w * 16 + nt * 8 + g;
                float v0 = vbuf[d * LDV + kl * 8 + c];
                float v1 = vbuf[d * LDV + kl * 8 + c + 4];
                uint32_t bh[2] = {f2tf(v0), f2tf(v1)};
                mma8(acco[0][nt], (const uint32_t*)&ap0f, bh);
                mma8(acco[1][nt], (const uint32_t*)&ap1f, bh);
            }
        }
        __syncthreads();
        if (wi < 3) fillV(wi + 1);
    }

    int pb = (b * NSPLIT + sp) * HH;
    if (lane == 0) {
#pragma unroll
        for (int hj = 0; hj < 4; hj++) {
            g_pm[pb + 4 * w + hj]   = m_r[hj];
            g_psum[pb + 4 * w + hj] = s_r[hj];
        }
    }
#pragma unroll
    for (int mt = 0; mt < 2; mt++)
#pragma unroll
        for (int nt = 0; nt < 2; nt++) {
            int h0 = mt * 16 + g;
            int dd = w * 16 + nt * 8 + 2 * c;
            g_po[(size_t)(pb + h0) * DD + dd]         = acco[mt][nt][0];
            g_po[(size_t)(pb + h0) * DD + dd + 1]     = acco[mt][nt][1];
            g_po[(size_t)(pb + h0 + 8) * DD + dd]     = acco[mt][nt][2];
            g_po[(size_t)(pb + h0 + 8) * DD + dd + 1] = acco[mt][nt][3];
        }
}

/* ---------------- combine (also zeroes `out` for the o-proj atomics) ------ */
__global__ void combine_kernel(const int* __restrict__ ci, float* __restrict__ out) {
    int bh = blockIdx.x;
    int b = bh >> 5, h = bh & 31;
    int d = threadIdx.x;
    out[bh * 128 + d] = 0.f;            /* 1024*128 == out_size */
    int nv = (ci[b] >> 8) + 1;
    float m = -1e30f;
    for (int s = 0; s < nv; s++)
        m = fmaxf(m, g_pm[(b * NSPLIT + s) * HH + h]);
    float S = 0.f, acc = 0.f;
    for (int s = 0; s < nv; s++) {
        int ib = (b * NSPLIT + s) * HH + h;
        float w = __expf(g_pm[ib] - m);
        S   += w * g_psum[ib];
        acc += w * g_po[(size_t)ib * DD + d];
    }
    g_attn[(b * HH + h) * DD + d] = acc / S;
}

/* ---------------- launch ------------------------------------------------- */
extern "C" void kernel_launch(void* const* d_in, const int* in_sizes, int n_in,
                              void* d_out, int out_size) {
    const float* x  = (const float*)d_in[0];
    const float* Kc = (const float*)d_in[1];
    const float* Vc = (const float*)d_in[2];
    const float* Wq = (const float*)d_in[3];
    const float* Wk = (const float*)d_in[4];
    const float* Wv = (const float*)d_in[5];
    const float* Wo = (const float*)d_in[6];
    const int*   ci = (const int*)d_in[7];
    float* out = (float*)d_out;

    float *qp, *ap;
    cudaGetSymbolAddress((void**)&qp, g_q);
    cudaGetSymbolAddress((void**)&ap, g_attn);

    cudaFuncSetAttribute(tgemm32<true>,
                         cudaFuncAttributeMaxDynamicSharedMemorySize, 101376);
    cudaFuncSetAttribute(tgemm32<false>,
                         cudaFuncAttributeMaxDynamicSharedMemorySize, 101376);
    cudaFuncSetAttribute(attn_kernel,
                         cudaFuncAttributeMaxDynamicSharedMemorySize, 104960);

    zero_kernel<<<512, 256>>>();
    tgemm32<true><<<dim3(16, SPLITK), 256, 101376>>>(x, Wq, qp, 4096);
    kvproj<<<dim3(2, 32), 256>>>(x, Wk, Wv);
    qprep_kernel<<<dim3(32, 4), 256>>>(ci);
    attn_kernel<<<dim3(32, NSPLIT), 256, 104960>>>(Kc, Vc, ci);
    combine_kernel<<<1024, 128>>>(ci, out);
    tgemm32<false><<<dim3(16, SPLITK), 256, 101376>>>(ap, Wo, out, 4096);
}

// round 16
// speedup vs baseline: 1.5235x; 1.0837x over previous
#include <cuda_runtime.h>
#include <math.h>
#include <stdint.h>

#define BB 32
#define FF 4096
#define HH 32
#define DD 128
#define LL 8192
#define NSPLIT 32
#define CH (LL/NSPLIT)          /* 256 */
#define WIN 64
#define LDW 72                  /* K window stride (floats) */
#define LDV 68                  /* V window stride (floats) */
#define LDP 68                  /* psh row stride (col 64 = corr) */
#define SCALE 0.08838834764831845f

/* ---------------- scratch ------------------------------------------------ */
__device__ float g_q[BB*HH*DD];
__device__ float g_qf[BB*HH*DD];    /* packed tf32 q fragments */
__device__ float g_k[BB*DD];
__device__ float g_kr[BB*DD];       /* roped k */
__device__ float g_v[BB*DD];
__device__ float g_attn[BB*HH*DD];
__device__ float g_pm[BB*NSPLIT*HH];
__device__ float g_psum[BB*NSPLIT*HH];
__device__ float g_po[BB*NSPLIT*HH*DD];
__device__ float g_freq[64];

/* ---------------- helpers ------------------------------------------------ */
__device__ __forceinline__ uint32_t s2u(const void* p) {
    return (uint32_t)__cvta_generic_to_shared(p);
}
__device__ __forceinline__ void cpa16(uint32_t s, const void* g) {
    asm volatile("cp.async.cg.shared.global [%0], [%1], 16;" :: "r"(s), "l"(g));
}
__device__ __forceinline__ void cpcommit() { asm volatile("cp.async.commit_group;"); }
__device__ __forceinline__ void cpwait0()  { asm volatile("cp.async.wait_group 0;"); }
__device__ __forceinline__ void cpwait1()  { asm volatile("cp.async.wait_group 1;"); }

__device__ __forceinline__ uint32_t f2tf(float x) {
    uint32_t r; asm("cvt.rna.tf32.f32 %0, %1;" : "=r"(r) : "f"(x)); return r;
}
__device__ __forceinline__ float tff(float x) { return __uint_as_float(f2tf(x)); }
__device__ __forceinline__ void mma8(float* d, const uint32_t* a, const uint32_t* b) {
    asm volatile("mma.sync.aligned.m16n8k8.row.col.f32.tf32.tf32.f32 "
        "{%0,%1,%2,%3},{%4,%5,%6,%7},{%8,%9},{%0,%1,%2,%3};"
        : "+f"(d[0]), "+f"(d[1]), "+f"(d[2]), "+f"(d[3])
        : "r"(a[0]), "r"(a[1]), "r"(a[2]), "r"(a[3]), "r"(b[0]), "r"(b[1]));
}

/* ---------------- zero + freq table -------------------------------------- */
__global__ void zero_kernel() {
    int i = blockIdx.x * 256 + threadIdx.x;
    g_q[i] = 0.f;
    if (i < BB*DD) { g_k[i] = 0.f; g_v[i] = 0.f; }
    if (i < 64) g_freq[i] = (float)exp(-(double)i * 0.14391156831212787);
}

/* ---------------- fused q-proj tgemm (blocks 0..255) + kvproj (256..319) --
 * tgemm: 2-term A x single W, N-tile 256, SPLITK 16 (identical to R15).
 * kvproj: fp32 FFMA K/V projection using a prefix of the dynamic smem.    */
#define SPLITK 16
#define KSL (FF/SPLITK)          /* 256 */
__global__ __launch_bounds__(256, 2) void qkvproj_kernel(
        const float* __restrict__ A, const float* __restrict__ Wq,
        const float* __restrict__ Wk, const float* __restrict__ Wv,
        float* __restrict__ Cq) {
    extern __shared__ float sm[];
    int bx = blockIdx.x;
    int t = threadIdx.x;

    if (bx >= 256) {
        /* ------------- kvproj branch ------------- */
        int kv = bx - 256;
        const float* W = (kv >> 5) ? Wv : Wk;
        float* C = (kv >> 5) ? g_v : g_k;
        int k0 = (kv & 31) * 128;
        float* As = sm;             /* [32][36] */
        float* Ws = sm + 32 * 36;   /* [32][132] */
        int mi = t >> 5, ni = t & 31;
        float acc[4][4];
#pragma unroll
        for (int i = 0; i < 4; i++)
#pragma unroll
            for (int j = 0; j < 4; j++) acc[i][j] = 0.f;

        for (int kb = 0; kb < 128; kb += 32) {
            int kg = k0 + kb;
#pragma unroll
            for (int p = 0; p < 4; p++) {
                int i = t + p * 256;
                As[(i & 31) * 36 + (i >> 5)] = A[(i >> 5) * FF + kg + (i & 31)];
            }
#pragma unroll
            for (int p = 0; p < 4; p++) {
                int i = t + p * 256;
                int kk = i >> 5, nq = i & 31;
                *(float4*)&Ws[kk * 132 + nq * 4] =
                    *(const float4*)&W[(kg + kk) * DD + nq * 4];
            }
            __syncthreads();
#pragma unroll
            for (int kk = 0; kk < 32; kk++) {
                float4 a = *(float4*)&As[kk * 36 + mi * 4];
                float4 w = *(float4*)&Ws[kk * 132 + ni * 4];
                acc[0][0] += a.x*w.x; acc[0][1] += a.x*w.y; acc[0][2] += a.x*w.z; acc[0][3] += a.x*w.w;
                acc[1][0] += a.y*w.x; acc[1][1] += a.y*w.y; acc[1][2] += a.y*w.z; acc[1][3] += a.y*w.w;
                acc[2][0] += a.z*w.x; acc[2][1] += a.z*w.y; acc[2][2] += a.z*w.z; acc[2][3] += a.z*w.w;
                acc[3][0] += a.w*w.x; acc[3][1] += a.w*w.y; acc[3][2] += a.w*w.z; acc[3][3] += a.w*w.w;
            }
            __syncthreads();
        }
#pragma unroll
        for (int i = 0; i < 4; i++)
#pragma unroll
            for (int j = 0; j < 4; j++)
                atomicAdd(&C[(mi * 4 + i) * DD + ni * 4 + j], acc[i][j]);
        return;
    }

    /* ------------- q-proj tgemm branch (2-term A x single W) ------------- */
    float* As = sm;                  /* 8448 floats */
    float* Ws = sm + 8448;           /* 2 x 8448 floats */
    uint32_t ws_u = s2u(Ws);

    int n0 = (bx & 15) * 256;
    int k0 = (bx >> 4) * KSL;
    int wp = t >> 5, lane = t & 31;
    int g = lane >> 2, c = lane & 3;

#pragma unroll
    for (int p = 0; p < 32; p++) {
        int i = t + p * 256;
        int m = i >> 8, k = i & 255;
        As[k * 33 + m] = A[m * FF + k0 + k];
    }
    auto loadW = [&](int kb, int buf) {
        const float* src = Wq + (size_t)(k0 + kb * 32) * FF + n0;
#pragma unroll
        for (int p = 0; p < 8; p++) {
            int ci = t + p * 256;
            int kk = ci >> 6, u = ci & 63;
            cpa16(ws_u + (uint32_t)(buf * 8448 + kk * 264 + 4 * u) * 4,
                  src + (size_t)kk * FF + 4 * u);
        }
        cpcommit();
    };
    loadW(0, 0);
    loadW(1, 1);

    float acc[2][4][4];
#pragma unroll
    for (int mt = 0; mt < 2; mt++)
#pragma unroll
        for (int nt = 0; nt < 4; nt++)
#pragma unroll
            for (int r = 0; r < 4; r++) acc[mt][nt][r] = 0.f;

    for (int kb = 0; kb < 8; kb++) {
        if (kb == 7) cpwait0(); else cpwait1();
        __syncthreads();
        const float* wsb = Ws + (kb & 1) * 8448;

#pragma unroll
        for (int ks = 0; ks < 4; ks++) {
            int kg = kb * 32 + ks * 8;
            uint32_t ahi[2][4], alo[2][4];
#pragma unroll
            for (int mt = 0; mt < 2; mt++) {
                float a0 = As[(kg + c)     * 33 + mt * 16 + g];
                float a1 = As[(kg + c)     * 33 + mt * 16 + g + 8];
                float a2 = As[(kg + c + 4) * 33 + mt * 16 + g];
                float a3 = As[(kg + c + 4) * 33 + mt * 16 + g + 8];
                ahi[mt][0] = f2tf(a0);
                ahi[mt][1] = f2tf(a1);
                ahi[mt][2] = f2tf(a2);
                ahi[mt][3] = f2tf(a3);
                alo[mt][0] = f2tf(a0 - __uint_as_float(ahi[mt][0]));
                alo[mt][1] = f2tf(a1 - __uint_as_float(ahi[mt][1]));
                alo[mt][2] = f2tf(a2 - __uint_as_float(ahi[mt][2]));
                alo[mt][3] = f2tf(a3 - __uint_as_float(ahi[mt][3]));
            }
#pragma unroll
            for (int nt = 0; nt < 4; nt++) {
                float b0 = wsb[(ks * 8 + c)     * 264 + wp * 32 + nt * 8 + g];
                float b1 = wsb[(ks * 8 + c + 4) * 264 + wp * 32 + nt * 8 + g];
                uint32_t bhi[2] = {f2tf(b0), f2tf(b1)};
#pragma unroll
                for (int mt = 0; mt < 2; mt++) {
                    mma8(acc[mt][nt], ahi[mt], bhi);
                    mma8(acc[mt][nt], alo[mt], bhi);
                }
            }
        }
        __syncthreads();
        if (kb < 6) loadW(kb + 2, kb & 1);
    }
#pragma unroll
    for (int mt = 0; mt < 2; mt++)
#pragma unroll
        for (int nt = 0; nt < 4; nt++) {
            int row = mt * 16 + g;
            int col = n0 + wp * 32 + nt * 8 + 2 * c;
            atomicAdd(&Cq[(row)     * FF + col],     acc[mt][nt][0]);
            atomicAdd(&Cq[(row)     * FF + col + 1], acc[mt][nt][1]);
            atomicAdd(&Cq[(row + 8) * FF + col],     acc[mt][nt][2]);
            atomicAdd(&Cq[(row + 8) * FF + col + 1], acc[mt][nt][3]);
        }
}

/* ---------------- o-proj tgemm (fragment-packed single-term A) ------------ */
__global__ __launch_bounds__(256, 2) void ogemm_kernel(
        const float* __restrict__ A, const float* __restrict__ W,
        float* __restrict__ C) {
    extern __shared__ float sm[];
    float* As = sm;
    float* Ws = sm + 8448;
    const float4* As4 = (const float4*)As;
    uint32_t ws_u = s2u(Ws);

    int n0 = blockIdx.x * 256;
    int k0 = blockIdx.y * KSL;
    int t = threadIdx.x, wp = t >> 5, lane = t & 31;
    int g = lane >> 2, c = lane & 3;

#pragma unroll
    for (int p = 0; p < 32; p++) {
        int i = t + p * 256;
        int m = i >> 8, k = i & 255;
        float val = tff(A[m * FF + k0 + k]);
        int kslot = k >> 3, c2 = k & 3, hi4 = (k >> 2) & 1;
        int mt = m >> 4, g2 = m & 7, m8 = (m >> 3) & 1;
        int fidx = (kslot * 2 + mt) * 32 + c2 * 8 + ((g2 + 2 * c2) & 7);
        As[fidx * 4 + hi4 * 2 + m8] = val;
    }
    auto loadW = [&](int kb, int buf) {
        const float* src = W + (size_t)(k0 + kb * 32) * FF + n0;
#pragma unroll
        for (int p = 0; p < 8; p++) {
            int ci = t + p * 256;
            int kk = ci >> 6, u = ci & 63;
            cpa16(ws_u + (uint32_t)(buf * 8448 + kk * 264 + 4 * u) * 4,
                  src + (size_t)kk * FF + 4 * u);
        }
        cpcommit();
    };
    loadW(0, 0);
    loadW(1, 1);

    int swz = c * 8 + ((g + 2 * c) & 7);

    float acc[2][4][4];
#pragma unroll
    for (int mt = 0; mt < 2; mt++)
#pragma unroll
        for (int nt = 0; nt < 4; nt++)
#pragma unroll
            for (int r = 0; r < 4; r++) acc[mt][nt][r] = 0.f;

    for (int kb = 0; kb < 8; kb++) {
        if (kb == 7) cpwait0(); else cpwait1();
        __syncthreads();
        const float* wsb = Ws + (kb & 1) * 8448;

#pragma unroll
        for (int ks = 0; ks < 4; ks++) {
            int kslot = kb * 4 + ks;
            uint32_t ahi[2][4];
            float4 af0 = As4[(kslot * 2 + 0) * 32 + swz];
            float4 af1 = As4[(kslot * 2 + 1) * 32 + swz];
            ahi[0][0] = __float_as_uint(af0.x); ahi[0][1] = __float_as_uint(af0.y);
            ahi[0][2] = __float_as_uint(af0.z); ahi[0][3] = __float_as_uint(af0.w);
            ahi[1][0] = __float_as_uint(af1.x); ahi[1][1] = __float_as_uint(af1.y);
            ahi[1][2] = __float_as_uint(af1.z); ahi[1][3] = __float_as_uint(af1.w);
#pragma unroll
            for (int nt = 0; nt < 4; nt++) {
                float b0 = wsb[(ks * 8 + c)     * 264 + wp * 32 + nt * 8 + g];
                float b1 = wsb[(ks * 8 + c + 4) * 264 + wp * 32 + nt * 8 + g];
                uint32_t bhi[2] = {f2tf(b0), f2tf(b1)};
                mma8(acc[0][nt], ahi[0], bhi);
                mma8(acc[1][nt], ahi[1], bhi);
            }
        }
        __syncthreads();
        if (kb < 6) loadW(kb + 2, kb & 1);
    }
#pragma unroll
    for (int mt = 0; mt < 2; mt++)
#pragma unroll
        for (int nt = 0; nt < 4; nt++) {
            int row = mt * 16 + g;
            int col = n0 + wp * 32 + nt * 8 + 2 * c;
            atomicAdd(&C[(row)     * FF + col],     acc[mt][nt][0]);
            atomicAdd(&C[(row)     * FF + col + 1], acc[mt][nt][1]);
            atomicAdd(&C[(row + 8) * FF + col],     acc[mt][nt][2]);
            atomicAdd(&C[(row + 8) * FF + col + 1], acc[mt][nt][3]);
        }
}

/* ---------------- qprep v3: MLP-batched loads, grid (32,4) ---------------- */
__global__ __launch_bounds__(256) void qprep_kernel(const int* __restrict__ ci) {
    int b = blockIdx.x, seg = blockIdx.y, t = threadIdx.x;
    float pos = (float)ci[b];
    const float* qb = g_q + b * HH * DD;
    float4* qf4 = (float4*)(g_qf + b * HH * DD);

    int fid = seg * 256 + t;
    int kd = fid >> 6, mt = (fid >> 5) & 1, cc = (fid >> 3) & 3, gg = fid & 7;
    int r0 = mt * 16 + gg, r1 = r0 + 8;
    int d0 = 8 * kd + cc, d1 = d0 + 4;

    float a00 = qb[r0 * DD + d0];
    float a01 = qb[r1 * DD + d0];
    float o00 = qb[r0 * DD + (d0 ^ 64)];
    float o01 = qb[r1 * DD + (d0 ^ 64)];
    float a10 = qb[r0 * DD + d1];
    float a11 = qb[r1 * DD + d1];
    float o10 = qb[r0 * DD + (d1 ^ 64)];
    float o11 = qb[r1 * DD + (d1 ^ 64)];
    float f0 = g_freq[d0 & 63], f1 = g_freq[d1 & 63];

    float s0, c0, s1, c1;
    sincosf(pos * f0, &s0, &c0);
    sincosf(pos * f1, &s1, &c1);

    float sgn0 = (d0 < 64) ? -1.f : 1.f;
    float sgn1 = (d1 < 64) ? -1.f : 1.f;
    float4 hi;
    hi.x = tff((a00 * c0 + sgn0 * o00 * s0) * SCALE);
    hi.y = tff((a01 * c0 + sgn0 * o01 * s0) * SCALE);
    hi.z = tff((a10 * c1 + sgn1 * o10 * s1) * SCALE);
    hi.w = tff((a11 * c1 + sgn1 * o11 * s1) * SCALE);
    int sfid = kd * 64 + mt * 32 + cc * 8 + ((gg + 2 * cc) & 7);
    qf4[sfid] = hi;

    if (seg == 0 && t < 128) {
        float a = g_k[b * DD + t];
        float o = g_k[b * DD + (t ^ 64)];
        float si, co;
        sincosf(pos * g_freq[t & 63], &si, &co);
        g_kr[b * DD + t] = (t < 64) ? (a * co - o * si) : (a * co + o * si);
    }
}

/* ---------------- flash-decode attention v8 (unchanged) ------------------- */
__global__ __launch_bounds__(256, 2) void attn_kernel(
        const float* __restrict__ Kc, const float* __restrict__ Vc,
        const int* __restrict__ ci) {
    extern __shared__ float sm[];
    float4* qfh4 = (float4*)sm;
    float*  psh  = sm + 4096;
    float*  ppkf = sm + 6272;
    float4* ppk4 = (float4*)ppkf;
    float*  kbuf = sm + 8320;
    float*  vbuf = sm + 17536;

    int b = blockIdx.x, sp = blockIdx.y;
    int idx = ci[b];
    int c0  = sp * CH;
    if (c0 > idx) return;

    int t = threadIdx.x, w = t >> 5, lane = t & 31;
    int g = lane >> 2, c = lane & 3;

    const float* Kb = Kc + (size_t)b * DD * LL;
    const float* Vb = Vc + (size_t)b * DD * LL;

    auto fillK = [&](int wi) {
        uint32_t dst = s2u(kbuf);
        const float* src = Kb + c0 + wi * WIN;
#pragma unroll
        for (int p = 0; p < 8; p++) {
            int i = t + p * 256; int d = i >> 4, u = i & 15;
            cpa16(dst + (uint32_t)(d * LDW + 4 * u) * 4, src + (size_t)d * LL + 4 * u);
        }
        cpcommit();
    };
    auto fillV = [&](int wi) {
        uint32_t dst = s2u(vbuf);
        const float* src = Vb + c0 + wi * WIN;
#pragma unroll
        for (int p = 0; p < 8; p++) {
            int i = t + p * 256; int d = i >> 4, u = i & 15;
            cpa16(dst + (uint32_t)(d * LDV + 4 * u) * 4, src + (size_t)d * LL + 4 * u);
        }
        cpcommit();
    };

    {
        uint32_t dst = s2u(qfh4);
        const float* src = g_qf + b * HH * DD;
#pragma unroll
        for (int p = 0; p < 4; p++) {
            int i = t + p * 256;
            cpa16(dst + (uint32_t)i * 16, src + i * 4);
        }
        cpcommit();
    }
    fillK(0);
    fillV(0);

    int swz = c * 8 + ((g + 2 * c) & 7);

    float m_r[4] = {-1e30f, -1e30f, -1e30f, -1e30f};
    float s_r[4] = {0.f, 0.f, 0.f, 0.f};
    float acco[2][2][4];
#pragma unroll
    for (int mt = 0; mt < 2; mt++)
#pragma unroll
        for (int nt = 0; nt < 2; nt++)
#pragma unroll
            for (int r = 0; r < 4; r++) acco[mt][nt][r] = 0.f;

    for (int wi = 0; wi < 4; wi++) {
        int l0w = c0 + wi * WIN;
        int hot = (idx >= l0w) && (idx < l0w + WIN);
        int li = idx - l0w;

        cpwait1();
        __syncthreads();
        if (hot) {
            if (t < 128) kbuf[t * LDW + li] += g_kr[b * DD + t];
            __syncthreads();
        }

        float accq[2][4];
#pragma unroll
        for (int mt = 0; mt < 2; mt++)
#pragma unroll
            for (int r = 0; r < 4; r++) accq[mt][r] = 0.f;

#pragma unroll
        for (int kd = 0; kd < 16; kd++) {
            float4 ah0 = qfh4[kd * 64 +      swz];
            float4 ah1 = qfh4[kd * 64 + 32 + swz];
            float b0 = kbuf[(kd * 8 + c)     * LDW + w * 8 + g];
            float b1 = kbuf[(kd * 8 + c + 4) * LDW + w * 8 + g];
            uint32_t bb[2] = {f2tf(b0), f2tf(b1)};
            mma8(accq[0], (const uint32_t*)&ah0, bb);
            mma8(accq[1], (const uint32_t*)&ah1, bb);
        }
#pragma unroll
        for (int mt = 0; mt < 2; mt++) {
            int r0 = mt * 16 + g, cb = w * 8 + 2 * c;
            psh[r0 * LDP + cb]           = accq[mt][0];
            psh[r0 * LDP + cb + 1]       = accq[mt][1];
            psh[(r0 + 8) * LDP + cb]     = accq[mt][2];
            psh[(r0 + 8) * LDP + cb + 1] = accq[mt][3];
        }
        __syncthreads();
        if (wi < 3) fillK(wi + 1);

#pragma unroll
        for (int hj = 0; hj < 4; hj++) {
            int h = 4 * w + hj;
            float2 f = *(float2*)&psh[h * LDP + 2 * lane];
            if (l0w + WIN - 1 > idx) {
                int lb = l0w + 2 * lane;
                if (lb     > idx) f.x = -1e30f;
                if (lb + 1 > idx) f.y = -1e30f;
            }
            float tm = fmaxf(f.x, f.y);
            tm = fmaxf(tm, __shfl_xor_sync(0xffffffffu, tm, 16));
            tm = fmaxf(tm, __shfl_xor_sync(0xffffffffu, tm, 8));
            tm = fmaxf(tm, __shfl_xor_sync(0xffffffffu, tm, 4));
            tm = fmaxf(tm, __shfl_xor_sync(0xffffffffu, tm, 2));
            tm = fmaxf(tm, __shfl_xor_sync(0xffffffffu, tm, 1));
            float mn = fmaxf(m_r[hj], tm);
            float co = __expf(m_r[hj] - mn);
            float p0 = __expf(f.x - mn), p1 = __expf(f.y - mn);
            float ls = p0 + p1;
            ls += __shfl_xor_sync(0xffffffffu, ls, 16);
            ls += __shfl_xor_sync(0xffffffffu, ls, 8);
            ls += __shfl_xor_sync(0xffffffffu, ls, 4);
            ls += __shfl_xor_sync(0xffffffffu, ls, 2);
            ls += __shfl_xor_sync(0xffffffffu, ls, 1);
            s_r[hj] = s_r[hj] * co + ls;
            m_r[hj] = mn;

            int half = h >> 4, gp = h & 7, mt = (h >> 3) & 1;
            int kl = lane >> 2;
            int cpos0 = (2 * lane) & 7;
            int hi4 = cpos0 >> 2;
            int cp0 = cpos0 & 3, cp1 = cp0 + 1;
            int rowbase = (kl * 64 + half * 32 + ((gp + kl) & 7) * 4) * 4
                          + mt + 2 * hi4;
            int sk = (kl >> 1);
            ppkf[rowbase + ((cp0 + sk) & 3) * 4] = tff(p0);
            ppkf[rowbase + ((cp1 + sk) & 3) * 4] = tff(p1);
            if (lane == 0) psh[h * LDP + 64] = co;
        }

        if (wi == 3) cpwait0(); else cpwait1();
        __syncthreads();
        if (hot) {
            if (t < 128) vbuf[t * LDV + li] += g_v[b * DD + t];
            __syncthreads();
        }

        {
            float s0 = psh[(g)      * LDP + 64];
            float s1 = psh[(g + 8)  * LDP + 64];
            float s2 = psh[(g + 16) * LDP + 64];
            float s3 = psh[(g + 24) * LDP + 64];
#pragma unroll
            for (int nt = 0; nt < 2; nt++) {
                acco[0][nt][0] *= s0; acco[0][nt][1] *= s0;
                acco[0][nt][2] *= s1; acco[0][nt][3] *= s1;
                acco[1][nt][0] *= s2; acco[1][nt][1] *= s2;
                acco[1][nt][2] *= s3; acco[1][nt][3] *= s3;
            }
        }

#pragma unroll
        for (int kl = 0; kl < 8; kl++) {
            int pidx = kl * 64 + ((g + kl) & 7) * 4 + ((c + (kl >> 1)) & 3);
            float4 ap0f = ppk4[pidx];
            float4 ap1f = ppk4[pidx + 32];
#pragma unroll
            for (int nt = 0; nt < 2; nt++) {
                int d = w * 16 + nt * 8 + g;
                float v0 = vbuf[d * LDV + kl * 8 + c];
                float v1 = vbuf[d * LDV + kl * 8 + c + 4];
                uint32_t bh[2] = {f2tf(v0), f2tf(v1)};
                mma8(acco[0][nt], (const uint32_t*)&ap0f, bh);
                mma8(acco[1][nt], (const uint32_t*)&ap1f, bh);
            }
        }
        __syncthreads();
        if (wi < 3) fillV(wi + 1);
    }

    int pb = (b * NSPLIT + sp) * HH;
    if (lane == 0) {
#pragma unroll
        for (int hj = 0; hj < 4; hj++) {
            g_pm[pb + 4 * w + hj]   = m_r[hj];
            g_psum[pb + 4 * w + hj] = s_r[hj];
        }
    }
#pragma unroll
    for (int mt = 0; mt < 2; mt++)
#pragma unroll
        for (int nt = 0; nt < 2; nt++) {
            int h0 = mt * 16 + g;
            int dd = w * 16 + nt * 8 + 2 * c;
            g_po[(size_t)(pb + h0) * DD + dd]         = acco[mt][nt][0];
            g_po[(size_t)(pb + h0) * DD + dd + 1]     = acco[mt][nt][1];
            g_po[(size_t)(pb + h0 + 8) * DD + dd]     = acco[mt][nt][2];
            g_po[(size_t)(pb + h0 + 8) * DD + dd + 1] = acco[mt][nt][3];
        }
}

/* ---------------- combine (also zeroes `out`) ----------------------------- */
__global__ void combine_kernel(const int* __restrict__ ci, float* __restrict__ out) {
    int bh = blockIdx.x;
    int b = bh >> 5, h = bh & 31;
    int d = threadIdx.x;
    out[bh * 128 + d] = 0.f;
    int nv = (ci[b] >> 8) + 1;
    float m = -1e30f;
    for (int s = 0; s < nv; s++)
        m = fmaxf(m, g_pm[(b * NSPLIT + s) * HH + h]);
    float S = 0.f, acc = 0.f;
    for (int s = 0; s < nv; s++) {
        int ib = (b * NSPLIT + s) * HH + h;
        float w = __expf(g_pm[ib] - m);
        S   += w * g_psum[ib];
        acc += w * g_po[(size_t)ib * DD + d];
    }
    g_attn[(b * HH + h) * DD + d] = acc / S;
}

/* ---------------- launch ------------------------------------------------- */
extern "C" void kernel_launch(void* const* d_in, const int* in_sizes, int n_in,
                              void* d_out, int out_size) {
    const float* x  = (const float*)d_in[0];
    const float* Kc = (const float*)d_in[1];
    const float* Vc = (const float*)d_in[2];
    const float* Wq = (const float*)d_in[3];
    const float* Wk = (const float*)d_in[4];
    const float* Wv = (const float*)d_in[5];
    const float* Wo = (const float*)d_in[6];
    const int*   ci = (const int*)d_in[7];
    float* out = (float*)d_out;

    float *qp, *ap;
    cudaGetSymbolAddress((void**)&qp, g_q);
    cudaGetSymbolAddress((void**)&ap, g_attn);

    cudaFuncSetAttribute(qkvproj_kernel,
                         cudaFuncAttributeMaxDynamicSharedMemorySize, 101376);
    cudaFuncSetAttribute(ogemm_kernel,
                         cudaFuncAttributeMaxDynamicSharedMemorySize, 101376);
    cudaFuncSetAttribute(attn_kernel,
                         cudaFuncAttributeMaxDynamicSharedMemorySize, 104960);

    zero_kernel<<<512, 256>>>();
    qkvproj_kernel<<<320, 256, 101376>>>(x, Wq, Wk, Wv, qp);
    qprep_kernel<<<dim3(32, 4), 256>>>(ci);
    attn_kernel<<<dim3(32, NSPLIT), 256, 104960>>>(Kc, Vc, ci);
    combine_kernel<<<1024, 128>>>(ci, out);
    ogemm_kernel<<<dim3(16, SPLITK), 256, 101376>>>(ap, Wo, out);
}